// round 2
// baseline (speedup 1.0000x reference)
#include <cuda_runtime.h>
#include <cuda_bf16.h>
#include <math.h>

// Problem constants
#define BATCH 4
#define CIN   512     // C
#define CK    256
#define CV    256
#define QKV   768     // CK + CK + CV
#define NPIX  4096    // H*W
#define EPSBN 1e-5f

// ---------------- scratch (device globals; no allocation allowed) -------------
static __device__ float g_wT[CIN * QKV];            // [c][o] transposed qkv weights
static __device__ float g_bias[QKV];                // concat bq,bk,bv
static __device__ float g_wWT[CV * CIN];            // [cv][co] transposed wW
static __device__ float g_Z[(size_t)BATCH * QKV * NPIX];      // qkv raw / post-BN (50MB)
static __device__ float g_S[(size_t)BATCH * NPIX * NPIX];     // attention scores (268MB)
static __device__ float g_ctx[(size_t)BATCH * CV * NPIX];     // context (17MB)
static __device__ float g_bnA[2 * CK];              // per-channel scale (q then k)
static __device__ float g_bnB[2 * CK];              // per-channel shift

// ---------------- prep: transpose weights, concat bias ------------------------
__global__ void prep_kernel(const float* __restrict__ wq, const float* __restrict__ bq,
                            const float* __restrict__ wk, const float* __restrict__ bk,
                            const float* __restrict__ wv, const float* __restrict__ bv,
                            const float* __restrict__ wW) {
    int idx = blockIdx.x * blockDim.x + threadIdx.x;
    if (idx < QKV * CIN) {
        int o = idx % QKV;
        int c = idx / QKV;
        const float* w; int oo;
        if (o < CK)          { w = wq; oo = o; }
        else if (o < 2 * CK) { w = wk; oo = o - CK; }
        else                 { w = wv; oo = o - 2 * CK; }
        g_wT[idx] = w[oo * CIN + c];
    }
    if (idx < CV * CIN) {
        int co = idx % CIN;
        int cv = idx / CIN;
        g_wWT[idx] = wW[co * CV + cv];
    }
    if (idx < QKV) {
        g_bias[idx] = (idx < CK) ? bq[idx] : (idx < 2 * CK) ? bk[idx - CK] : bv[idx - 2 * CK];
    }
}

// ---------------- GEMM TN: C[i,j] = alpha * sum_k A[k*lda+i]*B[k*ldb+j] -------
// A: K x M (row-major), B: K x N (row-major), C: M x N (row-major)
#define BM 128
#define BN 128
#define BKT 8
#define TM 8
#define TNN 8

__global__ void __launch_bounds__(256)
gemm_tn(const float* __restrict__ A, const float* __restrict__ B, float* __restrict__ C,
        int M, int N, int K, int lda, int ldb, int ldc,
        long sA, long sB, long sC,
        const float* __restrict__ bias,
        const float* __restrict__ resid, long sR,
        float alpha)
{
    __shared__ float As[BKT][BM];
    __shared__ float Bs[BKT][BN];
    int bz = blockIdx.z;
    A += (long)bz * sA;
    B += (long)bz * sB;
    C += (long)bz * sC;
    if (resid) resid += (long)bz * sR;

    int i0 = blockIdx.y * BM;
    int j0 = blockIdx.x * BN;
    int tid = threadIdx.x;
    int tx = tid % 16, ty = tid / 16;

    float acc[TM][TNN];
    #pragma unroll
    for (int m = 0; m < TM; m++)
        #pragma unroll
        for (int n = 0; n < TNN; n++) acc[m][n] = 0.f;

    for (int k0 = 0; k0 < K; k0 += BKT) {
        #pragma unroll
        for (int r = 0; r < 4; r++) {
            int kk = r * 2 + tid / 128;
            int ii = tid % 128;
            As[kk][ii] = A[(long)(k0 + kk) * lda + i0 + ii];
            Bs[kk][ii] = B[(long)(k0 + kk) * ldb + j0 + ii];
        }
        __syncthreads();
        #pragma unroll
        for (int kk = 0; kk < BKT; kk++) {
            float a[TM], b[TNN];
            #pragma unroll
            for (int m = 0; m < TM; m++) a[m] = As[kk][ty * TM + m];
            #pragma unroll
            for (int n = 0; n < TNN; n++) b[n] = Bs[kk][tx * TNN + n];
            #pragma unroll
            for (int m = 0; m < TM; m++)
                #pragma unroll
                for (int n = 0; n < TNN; n++)
                    acc[m][n] += a[m] * b[n];
        }
        __syncthreads();
    }

    #pragma unroll
    for (int m = 0; m < TM; m++) {
        int i = i0 + ty * TM + m;
        float bi = bias ? bias[i] : 0.f;
        #pragma unroll
        for (int n = 0; n < TNN; n++) {
            int j = j0 + tx * TNN + n;
            float v = acc[m][n] * alpha + bi;
            if (resid) v += resid[(long)i * ldc + j];
            C[(long)i * ldc + j] = v;
        }
    }
}

// ---------------- GEMM NT: C[i,j] = sum_k A[i*lda+k]*B[j*ldb+k] ---------------
// A: M x K (row-major), B: N x K (row-major), C: M x N (row-major)
__global__ void __launch_bounds__(256)
gemm_nt(const float* __restrict__ A, const float* __restrict__ B, float* __restrict__ C,
        int M, int N, int K, int lda, int ldb, int ldc,
        long sA, long sB, long sC)
{
    __shared__ float As[BKT][BM + 4];
    __shared__ float Bs[BKT][BN + 4];
    int bz = blockIdx.z;
    A += (long)bz * sA;
    B += (long)bz * sB;
    C += (long)bz * sC;

    int i0 = blockIdx.y * BM;
    int j0 = blockIdx.x * BN;
    int tid = threadIdx.x;
    int tx = tid % 16, ty = tid / 16;

    float acc[TM][TNN];
    #pragma unroll
    for (int m = 0; m < TM; m++)
        #pragma unroll
        for (int n = 0; n < TNN; n++) acc[m][n] = 0.f;

    for (int k0 = 0; k0 < K; k0 += BKT) {
        #pragma unroll
        for (int r = 0; r < 4; r++) {
            int t = r * 256 + tid;
            int ii = t / BKT;
            int kk = t % BKT;
            As[kk][ii] = A[(long)(i0 + ii) * lda + k0 + kk];
            Bs[kk][ii] = B[(long)(j0 + ii) * ldb + k0 + kk];
        }
        __syncthreads();
        #pragma unroll
        for (int kk = 0; kk < BKT; kk++) {
            float a[TM], b[TNN];
            #pragma unroll
            for (int m = 0; m < TM; m++) a[m] = As[kk][ty * TM + m];
            #pragma unroll
            for (int n = 0; n < TNN; n++) b[n] = Bs[kk][tx * TNN + n];
            #pragma unroll
            for (int m = 0; m < TM; m++)
                #pragma unroll
                for (int n = 0; n < TNN; n++)
                    acc[m][n] += a[m] * b[n];
        }
        __syncthreads();
    }

    #pragma unroll
    for (int m = 0; m < TM; m++) {
        int i = i0 + ty * TM + m;
        #pragma unroll
        for (int n = 0; n < TNN; n++) {
            int j = j0 + tx * TNN + n;
            C[(long)i * ldc + j] = acc[m][n];
        }
    }
}

// ---------------- BN stats over (B, N) for q and k channels --------------------
__global__ void bn_stats(const float* __restrict__ gq, const float* __restrict__ betaq,
                         const float* __restrict__ gk, const float* __restrict__ betak)
{
    int o = blockIdx.x;   // 0..511 : row o of each batch's Z (q rows 0..255, k rows 256..511)
    int t = threadIdx.x;
    __shared__ float rs[256], rq[256];
    float s = 0.f, sq = 0.f;
    for (int b = 0; b < BATCH; b++) {
        const float* p = g_Z + ((long)b * QKV + o) * NPIX;
        for (int i = t; i < NPIX; i += 256) {
            float v = p[i];
            s += v;
            sq += v * v;
        }
    }
    rs[t] = s; rq[t] = sq;
    __syncthreads();
    for (int st = 128; st > 0; st >>= 1) {
        if (t < st) { rs[t] += rs[t + st]; rq[t] += rq[t + st]; }
        __syncthreads();
    }
    if (t == 0) {
        float cnt = (float)(BATCH * NPIX);
        float mean = rs[0] / cnt;
        float var = rq[0] / cnt - mean * mean;
        float inv = rsqrtf(var + EPSBN);
        float gamma = (o < CK) ? gq[o] : gk[o - CK];
        float beta  = (o < CK) ? betaq[o] : betak[o - CK];
        g_bnA[o] = gamma * inv;
        g_bnB[o] = beta - mean * gamma * inv;
    }
}

// ---------------- BN apply + ReLU in place on q,k rows of Z -------------------
__global__ void bn_apply(void)
{
    long idx = (long)blockIdx.x * blockDim.x + threadIdx.x;
    // total: BATCH * 512 * NPIX
    int n = (int)(idx % NPIX);
    int o = (int)((idx / NPIX) % (2 * CK));
    int b = (int)(idx / ((long)NPIX * 2 * CK));
    long off = ((long)b * QKV + o) * NPIX + n;
    float z = g_Z[off] * g_bnA[o] + g_bnB[o];
    g_Z[off] = z > 0.f ? z : 0.f;
}

// ---------------- row softmax over last dim of S ------------------------------
__global__ void __launch_bounds__(256) softmax_rows(void)
{
    long row = blockIdx.x;                   // b*NPIX + n
    float* p = g_S + row * NPIX;
    __shared__ float buf[NPIX];
    __shared__ float red[256];
    int t = threadIdx.x;

    float mx = -1e30f;
    for (int i = t; i < NPIX; i += 256) {
        float v = p[i];
        buf[i] = v;
        mx = fmaxf(mx, v);
    }
    red[t] = mx;
    __syncthreads();
    for (int s = 128; s > 0; s >>= 1) {
        if (t < s) red[t] = fmaxf(red[t], red[t + s]);
        __syncthreads();
    }
    mx = red[0];
    __syncthreads();

    float sum = 0.f;
    for (int i = t; i < NPIX; i += 256) {
        float e = __expf(buf[i] - mx);
        buf[i] = e;
        sum += e;
    }
    red[t] = sum;
    __syncthreads();
    for (int s = 128; s > 0; s >>= 1) {
        if (t < s) red[t] += red[t + s];
        __syncthreads();
    }
    float inv = 1.f / red[0];
    for (int i = t; i < NPIX; i += 256) p[i] = buf[i] * inv;
}

// ---------------- launch ------------------------------------------------------
extern "C" void kernel_launch(void* const* d_in, const int* in_sizes, int n_in,
                              void* d_out, int out_size)
{
    const float* x     = (const float*)d_in[0];
    const float* wq    = (const float*)d_in[1];
    const float* bq    = (const float*)d_in[2];
    const float* gq    = (const float*)d_in[3];
    const float* betaq = (const float*)d_in[4];
    const float* wk    = (const float*)d_in[5];
    const float* bk    = (const float*)d_in[6];
    const float* gk    = (const float*)d_in[7];
    const float* betak = (const float*)d_in[8];
    const float* wv    = (const float*)d_in[9];
    const float* bv    = (const float*)d_in[10];
    const float* wW    = (const float*)d_in[11];
    const float* bW    = (const float*)d_in[12];
    float* out = (float*)d_out;

    float *pwT, *pbias, *pwWT, *pZ, *pS, *pctx;
    cudaGetSymbolAddress((void**)&pwT, g_wT);
    cudaGetSymbolAddress((void**)&pbias, g_bias);
    cudaGetSymbolAddress((void**)&pwWT, g_wWT);
    cudaGetSymbolAddress((void**)&pZ, g_Z);
    cudaGetSymbolAddress((void**)&pS, g_S);
    cudaGetSymbolAddress((void**)&pctx, g_ctx);

    // 1. transpose weights / concat bias
    prep_kernel<<<(QKV * CIN + 255) / 256, 256>>>(wq, bq, wk, bk, wv, bv, wW);

    // 2. qkv projection: Z[b, o, n] = sum_c wT[c, o] * x[b, c, n] + bias[o]
    {
        dim3 grid(NPIX / BN, QKV / BM, BATCH);
        gemm_tn<<<grid, 256>>>(pwT, x, pZ,
                               QKV, NPIX, CIN, QKV, NPIX, NPIX,
                               0L, (long)CIN * NPIX, (long)QKV * NPIX,
                               pbias, nullptr, 0L, 1.0f);
    }

    // 3. BN stats + 4. BN apply + ReLU (q and k rows)
    bn_stats<<<2 * CK, 256>>>(gq, betaq, gk, betak);
    bn_apply<<<(int)(((long)BATCH * 2 * CK * NPIX) / 256), 256>>>();

    // 5. scores: S[b, n, m] = (1/16) * sum_c k[b, c, n] * q[b, c, m]
    {
        dim3 grid(NPIX / BN, NPIX / BM, BATCH);
        gemm_tn<<<grid, 256>>>(pZ + (long)CK * NPIX, pZ, pS,
                               NPIX, NPIX, CK, NPIX, NPIX, NPIX,
                               (long)QKV * NPIX, (long)QKV * NPIX, (long)NPIX * NPIX,
                               nullptr, nullptr, 0L, 0.0625f);
    }

    // 6. softmax over m
    softmax_rows<<<BATCH * NPIX, 256>>>();

    // 7. ctx[b, c, n] = sum_m v[b, c, m] * P[b, n, m]
    {
        dim3 grid(NPIX / BN, CV / BM, BATCH);
        gemm_nt<<<grid, 256>>>(pZ + (long)2 * CK * NPIX, pS, pctx,
                               CV, NPIX, NPIX, NPIX, NPIX, NPIX,
                               (long)QKV * NPIX, (long)NPIX * NPIX, (long)CV * NPIX);
    }

    // 8. out[b, co, n] = sum_cv wWT[cv, co] * ctx[b, cv, n] + bW[co] + x[b, co, n]
    {
        dim3 grid(NPIX / BN, CIN / BM, BATCH);
        gemm_tn<<<grid, 256>>>(pwWT, pctx, out,
                               CIN, NPIX, CV, CIN, NPIX, NPIX,
                               0L, (long)CV * NPIX, (long)CIN * NPIX,
                               bW, x, (long)CIN * NPIX, 1.0f);
    }
}

// round 5
// speedup vs baseline: 2.7864x; 2.7864x over previous
#include <cuda_runtime.h>
#include <cuda_bf16.h>
#include <cstdint>
#include <math.h>

#define BATCH 4
#define CIN   512
#define CK    256
#define CV    256
#define QKV   768
#define NPIX  4096
#define EPSBN 1e-5f

#define KP_X   1536   // 3*CIN  (hi/lo split)
#define KP_QK  768    // 3*CK
#define KP_CTX 768    // 3*CV

// split patterns:
//   weights / k:     [hi | lo | hi]   (pattern A)
//   activations / q: [hi | hi | lo]   (pattern B)
// dot(A_pat, B_pat) = hi*hi + lo*hi + hi*lo  ≈ exact product sum

// ---------------- scratch globals --------------------------------------------
static __device__ __nv_bfloat16 g_wqkv2[(size_t)QKV * KP_X];
static __device__ __nv_bfloat16 g_wW2[(size_t)CIN * KP_CTX];
static __device__ float g_bias[QKV];
static __device__ __nv_bfloat16 g_xt2[(size_t)BATCH * NPIX * KP_X];
static __device__ float g_Z[(size_t)BATCH * QKV * NPIX];
static __device__ float g_bnA[2 * CK], g_bnB[2 * CK];
static __device__ __nv_bfloat16 g_qt2[(size_t)BATCH * NPIX * KP_QK];
static __device__ __nv_bfloat16 g_kt2[(size_t)BATCH * NPIX * KP_QK];
static __device__ __nv_bfloat16 g_v2[(size_t)BATCH * CV * NPIX];     // plain bf16
static __device__ float g_S[(size_t)BATCH * NPIX * NPIX];
static __device__ __nv_bfloat16 g_P2[(size_t)BATCH * NPIX * NPIX];   // plain bf16
static __device__ float g_ctxt[(size_t)BATCH * NPIX * CV];
static __device__ __nv_bfloat16 g_ctx2[(size_t)BATCH * NPIX * KP_CTX];

// ---------------- helpers ----------------------------------------------------
__device__ __forceinline__ uint32_t smem_u32(const void* p) {
    uint32_t a;
    asm("{ .reg .u64 t; cvta.to.shared.u64 t, %1; cvt.u32.u64 %0, t; }" : "=r"(a) : "l"(p));
    return a;
}
__device__ __forceinline__ void cp16(uint32_t dst, const void* src) {
    asm volatile("cp.async.cg.shared.global [%0], [%1], 16;" :: "r"(dst), "l"(src));
}
__device__ __forceinline__ void cp_commit() { asm volatile("cp.async.commit_group;" ::: "memory"); }
__device__ __forceinline__ void cp_wait1()  { asm volatile("cp.async.wait_group 1;" ::: "memory"); }

__device__ __forceinline__ uint32_t lds32(uint32_t a) {
    uint32_t v;
    asm volatile("ld.shared.b32 %0, [%1];" : "=r"(v) : "r"(a));
    return v;
}
__device__ __forceinline__ void mma16816(float* d, const uint32_t* a, uint32_t b0, uint32_t b1) {
    asm volatile(
        "mma.sync.aligned.m16n8k16.row.col.f32.bf16.bf16.f32 "
        "{%0,%1,%2,%3}, {%4,%5,%6,%7}, {%8,%9}, {%0,%1,%2,%3};"
        : "+f"(d[0]), "+f"(d[1]), "+f"(d[2]), "+f"(d[3])
        : "r"(a[0]), "r"(a[1]), "r"(a[2]), "r"(a[3]), "r"(b0), "r"(b1));
}
__device__ __forceinline__ void bsplit(float v, __nv_bfloat16& h, __nv_bfloat16& l) {
    h = __float2bfloat16(v);
    l = __float2bfloat16(v - __bfloat162float(h));
}

// ---------------- generic bf16 NT GEMM on HMMA --------------------------------
// C[i,j] = alpha * sum_k A[i,k]*B[j,k] (+bias[i]) (+resid[i,j]); fp32 out.
// A: M x K row-major bf16, B: N x K row-major bf16, K % 32 == 0.
// CTA tile 128x128, BK=32, 8 warps (4x2), warp tile 32x64.
#define ROWB 80            // 64B data + 16B pad per smem row
#define OPB  10240         // bytes per operand per stage (128 * 80)
#define STG  20480         // bytes per stage (A + B)

__global__ void __launch_bounds__(256, 2)
gemm_bf16(const __nv_bfloat16* __restrict__ A, const __nv_bfloat16* __restrict__ B,
          float* __restrict__ C, int K, int nit, int ldc,
          size_t sA, size_t sB, size_t sC,
          const float* __restrict__ bias, const float* __restrict__ resid, size_t sR,
          float alpha)
{
    __shared__ __align__(16) char smem[2 * STG];
    uint32_t sb = smem_u32(smem);
    int tid = threadIdx.x, wid = tid >> 5, lane = tid & 31;
    int bz = blockIdx.z;
    int i0 = blockIdx.y * 128;
    int j0 = blockIdx.x * 128;

    const char* ap = (const char*)(A + sA * bz);
    const char* bp = (const char*)(B + sB * bz);

    const char* asrc[2]; uint32_t adst[2];
    const char* bsrc[2]; uint32_t bdst[2];
    #pragma unroll
    for (int jj = 0; jj < 2; jj++) {
        int idx = tid + 256 * jj, row = idx >> 2, seg = idx & 3;
        asrc[jj] = ap + ((size_t)(i0 + row) * K) * 2 + seg * 16;
        adst[jj] = sb + row * ROWB + seg * 16;
        bsrc[jj] = bp + ((size_t)(j0 + row) * K) * 2 + seg * 16;
        bdst[jj] = sb + OPB + row * ROWB + seg * 16;
    }

    int g = lane >> 2, tg = lane & 3;
    int mw = wid >> 1, nw = wid & 1;
    uint32_t aB = sb + (mw * 32 + g) * ROWB + tg * 4;
    uint32_t bB = sb + OPB + (nw * 64 + g) * ROWB + tg * 4;

    float acc[2][8][4];
    #pragma unroll
    for (int t = 0; t < 2; t++)
        #pragma unroll
        for (int j = 0; j < 8; j++)
            #pragma unroll
            for (int c = 0; c < 4; c++) acc[t][j][c] = 0.f;

    #pragma unroll
    for (int jj = 0; jj < 2; jj++) { cp16(adst[jj], asrc[jj]); cp16(bdst[jj], bsrc[jj]); }
    cp_commit();

    for (int it = 0; it < nit; it++) {
        if (it + 1 < nit) {
            size_t ko = (size_t)(it + 1) * 64;
            uint32_t so = ((it + 1) & 1) * STG;
            #pragma unroll
            for (int jj = 0; jj < 2; jj++) {
                cp16(adst[jj] + so, asrc[jj] + ko);
                cp16(bdst[jj] + so, bsrc[jj] + ko);
            }
        }
        cp_commit();
        cp_wait1();
        __syncthreads();

        uint32_t so = (it & 1) * STG;
        #pragma unroll
        for (int k16 = 0; k16 < 2; k16++) {
            uint32_t kb = k16 * 32;
            uint32_t a[2][4];
            #pragma unroll
            for (int t = 0; t < 2; t++) {
                uint32_t base = aB + so + t * (16 * ROWB) + kb;
                a[t][0] = lds32(base);
                a[t][1] = lds32(base + 8 * ROWB);
                a[t][2] = lds32(base + 16);
                a[t][3] = lds32(base + 8 * ROWB + 16);
            }
            #pragma unroll
            for (int j = 0; j < 8; j++) {
                uint32_t base = bB + so + j * (8 * ROWB) + kb;
                uint32_t b0 = lds32(base);
                uint32_t b1 = lds32(base + 16);
                mma16816(acc[0][j], a[0], b0, b1);
                mma16816(acc[1][j], a[1], b0, b1);
            }
        }
        __syncthreads();
    }

    float* cb = C + sC * bz;
    const float* rb = resid ? resid + sR * bz : nullptr;
    #pragma unroll
    for (int t = 0; t < 2; t++) {
        int r0 = i0 + mw * 32 + t * 16 + g;
        int r1 = r0 + 8;
        float bi0 = bias ? bias[r0] : 0.f;
        float bi1 = bias ? bias[r1] : 0.f;
        #pragma unroll
        for (int j = 0; j < 8; j++) {
            int c = j0 + nw * 64 + j * 8 + tg * 2;
            float v0 = acc[t][j][0] * alpha + bi0;
            float v1 = acc[t][j][1] * alpha + bi0;
            float v2 = acc[t][j][2] * alpha + bi1;
            float v3 = acc[t][j][3] * alpha + bi1;
            if (rb) {
                float2 x0 = *(const float2*)(rb + (size_t)r0 * ldc + c);
                float2 x1 = *(const float2*)(rb + (size_t)r1 * ldc + c);
                v0 += x0.x; v1 += x0.y; v2 += x1.x; v3 += x1.y;
            }
            *(float2*)(cb + (size_t)r0 * ldc + c) = make_float2(v0, v1);
            *(float2*)(cb + (size_t)r1 * ldc + c) = make_float2(v2, v3);
        }
    }
}

// ---------------- prep: weight split (pattern A) + bias concat ----------------
__global__ void __launch_bounds__(256) prep_w(
    const float* __restrict__ wq, const float* __restrict__ bq,
    const float* __restrict__ wk, const float* __restrict__ bk,
    const float* __restrict__ wv, const float* __restrict__ bv,
    const float* __restrict__ wW)
{
    int idx = blockIdx.x * 256 + threadIdx.x;   // < QKV*CIN
    {
        int o = idx / CIN, c = idx % CIN;
        float v = (o < CK) ? wq[o * CIN + c] : (o < 2 * CK) ? wk[(o - CK) * CIN + c]
                                                            : wv[(o - 2 * CK) * CIN + c];
        __nv_bfloat16 h, l; bsplit(v, h, l);
        __nv_bfloat16* orow = g_wqkv2 + (size_t)o * KP_X;
        orow[c] = h; orow[c + CIN] = l; orow[c + 2 * CIN] = h;   // pattern A
    }
    if (idx < CIN * CV) {
        int co = idx / CV, cv = idx % CV;
        float v = wW[co * CV + cv];
        __nv_bfloat16 h, l; bsplit(v, h, l);
        __nv_bfloat16* orow = g_wW2 + (size_t)co * KP_CTX;
        orow[cv] = h; orow[cv + CV] = l; orow[cv + 2 * CV] = h;  // pattern A
    }
    if (idx < QKV)
        g_bias[idx] = (idx < CK) ? bq[idx] : (idx < 2 * CK) ? bk[idx - CK] : bv[idx - 2 * CK];
}

// ---------------- x transpose -> bf16 split pattern B [b][n][c'] --------------
__global__ void __launch_bounds__(256) transpose_x(const float* __restrict__ x)
{
    __shared__ float tile[32][33];
    int b = blockIdx.z, c0 = blockIdx.y * 32, n0 = blockIdx.x * 32;
    int tx = threadIdx.x & 31, ty = threadIdx.x >> 5;
    const float* xp = x + ((size_t)b * CIN + c0) * NPIX + n0;
    #pragma unroll
    for (int r = ty; r < 32; r += 8) tile[r][tx] = xp[(size_t)r * NPIX + tx];
    __syncthreads();
    __nv_bfloat16* op = g_xt2 + ((size_t)b * NPIX + n0) * KP_X + c0;
    #pragma unroll
    for (int r = ty; r < 32; r += 8) {
        float v = tile[tx][r];
        __nv_bfloat16 h, l; bsplit(v, h, l);
        __nv_bfloat16* orow = op + (size_t)r * KP_X;
        orow[tx] = h; orow[tx + CIN] = h; orow[tx + 2 * CIN] = l;   // pattern B
    }
}

// ---------------- BN stats over (B,N) -----------------------------------------
__global__ void __launch_bounds__(256) bn_stats(
    const float* __restrict__ gq, const float* __restrict__ betaq,
    const float* __restrict__ gk, const float* __restrict__ betak)
{
    int o = blockIdx.x;
    int t = threadIdx.x;
    __shared__ float rs[256], rq[256];
    float s = 0.f, sq = 0.f;
    for (int b = 0; b < BATCH; b++) {
        const float* p = g_Z + ((size_t)b * QKV + o) * NPIX;
        for (int i = t; i < NPIX; i += 256) {
            float v = p[i];
            s += v; sq += v * v;
        }
    }
    rs[t] = s; rq[t] = sq;
    __syncthreads();
    for (int st = 128; st > 0; st >>= 1) {
        if (t < st) { rs[t] += rs[t + st]; rq[t] += rq[t + st]; }
        __syncthreads();
    }
    if (t == 0) {
        float cnt = (float)(BATCH * NPIX);
        float mean = rs[0] / cnt;
        float var = rq[0] / cnt - mean * mean;
        float inv = rsqrtf(var + EPSBN);
        float gamma = (o < CK) ? gq[o] : gk[o - CK];
        float beta  = (o < CK) ? betaq[o] : betak[o - CK];
        g_bnA[o] = gamma * inv;
        g_bnB[o] = beta - mean * gamma * inv;
    }
}

// ---------------- BN+ReLU + transpose + split: q pattern B, k pattern A -------
__global__ void __launch_bounds__(256) convert_qk()
{
    __shared__ float tile[32][33];
    int b = blockIdx.z, o0 = blockIdx.y * 32, n0 = blockIdx.x * 32;
    int tx = threadIdx.x & 31, ty = threadIdx.x >> 5;
    #pragma unroll
    for (int r = ty; r < 32; r += 8) {
        int o = o0 + r;
        float z = g_Z[((size_t)b * QKV + o) * NPIX + n0 + tx] * g_bnA[o] + g_bnB[o];
        tile[r][tx] = z > 0.f ? z : 0.f;
    }
    __syncthreads();
    bool isq = (o0 < CK);
    __nv_bfloat16* base = isq ? g_qt2 : g_kt2;
    int oc = o0 & (CK - 1);
    __nv_bfloat16* op = base + ((size_t)b * NPIX + n0) * KP_QK + oc;
    #pragma unroll
    for (int r = ty; r < 32; r += 8) {
        float v = tile[tx][r];
        __nv_bfloat16 h, l; bsplit(v, h, l);
        __nv_bfloat16* orow = op + (size_t)r * KP_QK;
        if (isq) { orow[tx] = h; orow[tx + CK] = h; orow[tx + 2 * CK] = l; }  // B
        else     { orow[tx] = h; orow[tx + CK] = l; orow[tx + 2 * CK] = h; }  // A
    }
}

// ---------------- v -> plain bf16 [b][c][m] -----------------------------------
__global__ void __launch_bounds__(256) convert_v()
{
    size_t idx = (size_t)blockIdx.x * 256 + threadIdx.x;   // BATCH*CV*NPIX
    int m = (int)(idx & (NPIX - 1));
    int c = (int)((idx >> 12) & (CV - 1));
    int b = (int)(idx >> 20);
    float v = g_Z[((size_t)b * QKV + 2 * CK + c) * NPIX + m];
    g_v2[idx] = __float2bfloat16(v);
}

// ---------------- softmax rows -> plain bf16 P --------------------------------
__global__ void __launch_bounds__(256) softmax_p()
{
    size_t row = blockIdx.x;
    const float* p = g_S + row * NPIX;
    __nv_bfloat16* o = g_P2 + row * (size_t)NPIX;
    __shared__ float buf[NPIX];
    __shared__ float red[256];
    int t = threadIdx.x;

    float mx = -1e30f;
    for (int i = t; i < NPIX; i += 256) { float v = p[i]; buf[i] = v; mx = fmaxf(mx, v); }
    red[t] = mx; __syncthreads();
    for (int s = 128; s > 0; s >>= 1) { if (t < s) red[t] = fmaxf(red[t], red[t + s]); __syncthreads(); }
    mx = red[0]; __syncthreads();

    float sum = 0.f;
    for (int i = t; i < NPIX; i += 256) { float e = __expf(buf[i] - mx); buf[i] = e; sum += e; }
    red[t] = sum; __syncthreads();
    for (int s = 128; s > 0; s >>= 1) { if (t < s) red[t] += red[t + s]; __syncthreads(); }
    float inv = 1.f / red[0];
    for (int i = t; i < NPIX; i += 256) o[i] = __float2bfloat16(buf[i] * inv);
}

// ---------------- ctx -> split pattern B [b][n][cv'] --------------------------
__global__ void __launch_bounds__(256) convert_ctx()
{
    size_t idx = (size_t)blockIdx.x * 256 + threadIdx.x;   // BATCH*NPIX*CV
    int c = (int)(idx & (CV - 1));
    size_t nrow = idx >> 8;
    float v = g_ctxt[idx];
    __nv_bfloat16 h, l; bsplit(v, h, l);
    __nv_bfloat16* o = g_ctx2 + nrow * KP_CTX;
    o[c] = h; o[c + CV] = h; o[c + 2 * CV] = l;   // pattern B
}

// ---------------- launch ------------------------------------------------------
extern "C" void kernel_launch(void* const* d_in, const int* in_sizes, int n_in,
                              void* d_out, int out_size)
{
    const float* x     = (const float*)d_in[0];
    const float* wq    = (const float*)d_in[1];
    const float* bq    = (const float*)d_in[2];
    const float* gq    = (const float*)d_in[3];
    const float* betaq = (const float*)d_in[4];
    const float* wk    = (const float*)d_in[5];
    const float* bk    = (const float*)d_in[6];
    const float* gk    = (const float*)d_in[7];
    const float* betak = (const float*)d_in[8];
    const float* wv    = (const float*)d_in[9];
    const float* bv    = (const float*)d_in[10];
    const float* wW    = (const float*)d_in[11];
    const float* bW    = (const float*)d_in[12];
    float* out = (float*)d_out;

    void *pwqkv2, *pwW2, *pbias, *pxt2, *pZ, *pqt2, *pkt2, *pv2, *pS, *pP2, *pctxt, *pctx2;
    cudaGetSymbolAddress(&pwqkv2, g_wqkv2);
    cudaGetSymbolAddress(&pwW2, g_wW2);
    cudaGetSymbolAddress(&pbias, g_bias);
    cudaGetSymbolAddress(&pxt2, g_xt2);
    cudaGetSymbolAddress(&pZ, g_Z);
    cudaGetSymbolAddress(&pqt2, g_qt2);
    cudaGetSymbolAddress(&pkt2, g_kt2);
    cudaGetSymbolAddress(&pv2, g_v2);
    cudaGetSymbolAddress(&pS, g_S);
    cudaGetSymbolAddress(&pP2, g_P2);
    cudaGetSymbolAddress(&pctxt, g_ctxt);
    cudaGetSymbolAddress(&pctx2, g_ctx2);

    // 1. prep weights/bias; transpose+split x
    prep_w<<<(QKV * CIN) / 256, 256>>>(wq, bq, wk, bk, wv, bv, wW);
    transpose_x<<<dim3(NPIX / 32, CIN / 32, BATCH), 256>>>(x);

    // 2. qkv projection: Z[o][n] = wqkv2[o,:] . xt2[n,:] + bias   (M=768,N=4096,K=1536)
    gemm_bf16<<<dim3(NPIX / 128, QKV / 128, BATCH), 256>>>(
        (const __nv_bfloat16*)pwqkv2, (const __nv_bfloat16*)pxt2, (float*)pZ,
        KP_X, KP_X / 32, NPIX,
        0, (size_t)NPIX * KP_X, (size_t)QKV * NPIX,
        (const float*)pbias, nullptr, 0, 1.0f);

    // 3. BN stats; 4. converts
    bn_stats<<<2 * CK, 256>>>(gq, betaq, gk, betak);
    convert_qk<<<dim3(NPIX / 32, (2 * CK) / 32, BATCH), 256>>>();
    convert_v<<<(BATCH * CV * NPIX) / 256, 256>>>();

    // 5. scores: S[n][m] = (1/16) kt2[n,:] . qt2[m,:]   (M=N=4096, K=768)
    gemm_bf16<<<dim3(NPIX / 128, NPIX / 128, BATCH), 256>>>(
        (const __nv_bfloat16*)pkt2, (const __nv_bfloat16*)pqt2, (float*)pS,
        KP_QK, KP_QK / 32, NPIX,
        (size_t)NPIX * KP_QK, (size_t)NPIX * KP_QK, (size_t)NPIX * NPIX,
        nullptr, nullptr, 0, 0.0625f);

    // 6. softmax + bf16 cast
    softmax_p<<<BATCH * NPIX, 256>>>();

    // 7. ctx^T[n][c] = P2[n,:] . v2[c,:]   (M=4096, N=256, K=4096, plain bf16)
    gemm_bf16<<<dim3(CV / 128, NPIX / 128, BATCH), 256>>>(
        (const __nv_bfloat16*)pP2, (const __nv_bfloat16*)pv2, (float*)pctxt,
        NPIX, NPIX / 32, CV,
        (size_t)NPIX * NPIX, (size_t)CV * NPIX, (size_t)NPIX * CV,
        nullptr, nullptr, 0, 1.0f);

    // ctx split for final conv
    convert_ctx<<<(BATCH * NPIX * CV) / 256, 256>>>();

    // 8. out[co][n] = wW2[co,:] . ctx2[n,:] + bW[co] + x[co][n]   (M=512,N=4096,K=768)
    gemm_bf16<<<dim3(NPIX / 128, CIN / 128, BATCH), 256>>>(
        (const __nv_bfloat16*)pwW2, (const __nv_bfloat16*)pctx2, out,
        KP_CTX, KP_CTX / 32, NPIX,
        0, (size_t)NPIX * KP_CTX, (size_t)CIN * NPIX,
        bW, x, (size_t)CIN * NPIX, 1.0f);
}

// round 6
// speedup vs baseline: 3.4683x; 1.2447x over previous
#include <cuda_runtime.h>
#include <cuda_fp16.h>
#include <cstdint>
#include <math.h>

#define BATCH 4
#define CIN   512
#define CK    256
#define CV    256
#define QKV   768
#define NPIX  4096
#define EPSBN 1e-5f

#define KP_X   1024   // 2*CIN  (fp16 hi/lo 2-term split)
#define KP_QK  512    // 2*CK
#define KP_CTX 512    // 2*CV

// 2-term split patterns (fp16):
//   A side (weights / k):     [hi | lo]
//   B side (activations / q): [hi | hi]
// dot = a_hi*b_hi + a_lo*b_hi = a * b_hi ; missing a*b_lo ~ 2^-11 rel, sqrt-cancels.

// ---------------- scratch globals --------------------------------------------
static __device__ __half g_wqkv2[(size_t)QKV * KP_X];
static __device__ __half g_wW2[(size_t)CIN * KP_CTX];
static __device__ float g_bias[QKV];
static __device__ __half g_xt2[(size_t)BATCH * NPIX * KP_X];
static __device__ float g_Z[(size_t)BATCH * QKV * NPIX];
static __device__ float g_bnA[2 * CK], g_bnB[2 * CK];
static __device__ __half g_qt2[(size_t)BATCH * NPIX * KP_QK];
static __device__ __half g_kt2[(size_t)BATCH * NPIX * KP_QK];
static __device__ __half g_v2[(size_t)BATCH * CV * NPIX];     // plain fp16
static __device__ float g_S[(size_t)BATCH * NPIX * NPIX];
static __device__ __half g_P2[(size_t)BATCH * NPIX * NPIX];   // plain fp16
static __device__ float g_ctxt[(size_t)BATCH * NPIX * CV];
static __device__ __half g_ctx2[(size_t)BATCH * NPIX * KP_CTX];

// ---------------- helpers ----------------------------------------------------
__device__ __forceinline__ uint32_t smem_u32(const void* p) {
    uint32_t a;
    asm("{ .reg .u64 t; cvta.to.shared.u64 t, %1; cvt.u32.u64 %0, t; }" : "=r"(a) : "l"(p));
    return a;
}
__device__ __forceinline__ void cp16(uint32_t dst, const void* src) {
    asm volatile("cp.async.cg.shared.global [%0], [%1], 16;" :: "r"(dst), "l"(src));
}
__device__ __forceinline__ void cp_commit() { asm volatile("cp.async.commit_group;" ::: "memory"); }
__device__ __forceinline__ void cp_wait1()  { asm volatile("cp.async.wait_group 1;" ::: "memory"); }

__device__ __forceinline__ uint32_t lds32(uint32_t a) {
    uint32_t v;
    asm volatile("ld.shared.b32 %0, [%1];" : "=r"(v) : "r"(a));
    return v;
}
__device__ __forceinline__ void mma16816(float* d, const uint32_t* a, uint32_t b0, uint32_t b1) {
    asm volatile(
        "mma.sync.aligned.m16n8k16.row.col.f32.f16.f16.f32 "
        "{%0,%1,%2,%3}, {%4,%5,%6,%7}, {%8,%9}, {%0,%1,%2,%3};"
        : "+f"(d[0]), "+f"(d[1]), "+f"(d[2]), "+f"(d[3])
        : "r"(a[0]), "r"(a[1]), "r"(a[2]), "r"(a[3]), "r"(b0), "r"(b1));
}
__device__ __forceinline__ void hsplit(float v, __half& h, __half& l) {
    h = __float2half(v);
    l = __float2half(v - __half2float(h));
}

// ---------------- generic fp16 NT GEMM on HMMA --------------------------------
// C[i,j] = alpha * sum_k A[i,k]*B[j,k] (+bias[i]) (+resid[i,j]); fp32 out.
// A: M x K row-major fp16, B: N x K row-major fp16, K % 32 == 0.
// CTA tile 128x128, BK=32, 8 warps (4x2), warp tile 32x64.
#define ROWB 80            // 64B data + 16B pad per smem row
#define OPB  10240
#define STG  20480

__global__ void __launch_bounds__(256, 2)
gemm_fp16(const __half* __restrict__ A, const __half* __restrict__ B,
          float* __restrict__ C, int K, int nit, int ldc,
          size_t sA, size_t sB, size_t sC,
          const float* __restrict__ bias, const float* __restrict__ resid, size_t sR,
          float alpha)
{
    __shared__ __align__(16) char smem[2 * STG];
    uint32_t sb = smem_u32(smem);
    int tid = threadIdx.x, wid = tid >> 5, lane = tid & 31;
    int bz = blockIdx.z;
    int i0 = blockIdx.y * 128;
    int j0 = blockIdx.x * 128;

    const char* ap = (const char*)(A + sA * bz);
    const char* bp = (const char*)(B + sB * bz);

    const char* asrc[2]; uint32_t adst[2];
    const char* bsrc[2]; uint32_t bdst[2];
    #pragma unroll
    for (int jj = 0; jj < 2; jj++) {
        int idx = tid + 256 * jj, row = idx >> 2, seg = idx & 3;
        asrc[jj] = ap + ((size_t)(i0 + row) * K) * 2 + seg * 16;
        adst[jj] = sb + row * ROWB + seg * 16;
        bsrc[jj] = bp + ((size_t)(j0 + row) * K) * 2 + seg * 16;
        bdst[jj] = sb + OPB + row * ROWB + seg * 16;
    }

    int g = lane >> 2, tg = lane & 3;
    int mw = wid >> 1, nw = wid & 1;
    uint32_t aB = sb + (mw * 32 + g) * ROWB + tg * 4;
    uint32_t bB = sb + OPB + (nw * 64 + g) * ROWB + tg * 4;

    float acc[2][8][4];
    #pragma unroll
    for (int t = 0; t < 2; t++)
        #pragma unroll
        for (int j = 0; j < 8; j++)
            #pragma unroll
            for (int c = 0; c < 4; c++) acc[t][j][c] = 0.f;

    #pragma unroll
    for (int jj = 0; jj < 2; jj++) { cp16(adst[jj], asrc[jj]); cp16(bdst[jj], bsrc[jj]); }
    cp_commit();

    for (int it = 0; it < nit; it++) {
        if (it + 1 < nit) {
            size_t ko = (size_t)(it + 1) * 64;
            uint32_t so = ((it + 1) & 1) * STG;
            #pragma unroll
            for (int jj = 0; jj < 2; jj++) {
                cp16(adst[jj] + so, asrc[jj] + ko);
                cp16(bdst[jj] + so, bsrc[jj] + ko);
            }
        }
        cp_commit();
        cp_wait1();
        __syncthreads();

        uint32_t so = (it & 1) * STG;
        #pragma unroll
        for (int k16 = 0; k16 < 2; k16++) {
            uint32_t kb = k16 * 32;
            uint32_t a[2][4];
            #pragma unroll
            for (int t = 0; t < 2; t++) {
                uint32_t base = aB + so + t * (16 * ROWB) + kb;
                a[t][0] = lds32(base);
                a[t][1] = lds32(base + 8 * ROWB);
                a[t][2] = lds32(base + 16);
                a[t][3] = lds32(base + 8 * ROWB + 16);
            }
            #pragma unroll
            for (int j = 0; j < 8; j++) {
                uint32_t base = bB + so + j * (8 * ROWB) + kb;
                uint32_t b0 = lds32(base);
                uint32_t b1 = lds32(base + 16);
                mma16816(acc[0][j], a[0], b0, b1);
                mma16816(acc[1][j], a[1], b0, b1);
            }
        }
        __syncthreads();
    }

    float* cb = C + sC * bz;
    const float* rb = resid ? resid + sR * bz : nullptr;
    #pragma unroll
    for (int t = 0; t < 2; t++) {
        int r0 = i0 + mw * 32 + t * 16 + g;
        int r1 = r0 + 8;
        float bi0 = bias ? bias[r0] : 0.f;
        float bi1 = bias ? bias[r1] : 0.f;
        #pragma unroll
        for (int j = 0; j < 8; j++) {
            int c = j0 + nw * 64 + j * 8 + tg * 2;
            float v0 = acc[t][j][0] * alpha + bi0;
            float v1 = acc[t][j][1] * alpha + bi0;
            float v2 = acc[t][j][2] * alpha + bi1;
            float v3 = acc[t][j][3] * alpha + bi1;
            if (rb) {
                float2 x0 = *(const float2*)(rb + (size_t)r0 * ldc + c);
                float2 x1 = *(const float2*)(rb + (size_t)r1 * ldc + c);
                v0 += x0.x; v1 += x0.y; v2 += x1.x; v3 += x1.y;
            }
            *(float2*)(cb + (size_t)r0 * ldc + c) = make_float2(v0, v1);
            *(float2*)(cb + (size_t)r1 * ldc + c) = make_float2(v2, v3);
        }
    }
}

// ---------------- prep: weight split (pattern A) + bias concat ----------------
__global__ void __launch_bounds__(256) prep_w(
    const float* __restrict__ wq, const float* __restrict__ bq,
    const float* __restrict__ wk, const float* __restrict__ bk,
    const float* __restrict__ wv, const float* __restrict__ bv,
    const float* __restrict__ wW)
{
    int idx = blockIdx.x * 256 + threadIdx.x;   // < QKV*CIN
    {
        int o = idx / CIN, c = idx % CIN;
        float v = (o < CK) ? wq[o * CIN + c] : (o < 2 * CK) ? wk[(o - CK) * CIN + c]
                                                            : wv[(o - 2 * CK) * CIN + c];
        __half h, l; hsplit(v, h, l);
        __half* orow = g_wqkv2 + (size_t)o * KP_X;
        orow[c] = h; orow[c + CIN] = l;                       // pattern A
    }
    if (idx < CIN * CV) {
        int co = idx / CV, cv = idx % CV;
        float v = wW[co * CV + cv];
        __half h, l; hsplit(v, h, l);
        __half* orow = g_wW2 + (size_t)co * KP_CTX;
        orow[cv] = h; orow[cv + CV] = l;                      // pattern A
    }
    if (idx < QKV)
        g_bias[idx] = (idx < CK) ? bq[idx] : (idx < 2 * CK) ? bk[idx - CK] : bv[idx - 2 * CK];
}

// ---------------- x transpose -> fp16 split pattern B [b][n][c'] --------------
__global__ void __launch_bounds__(256) transpose_x(const float* __restrict__ x)
{
    __shared__ float tile[32][33];
    int b = blockIdx.z, c0 = blockIdx.y * 32, n0 = blockIdx.x * 32;
    int tx = threadIdx.x & 31, ty = threadIdx.x >> 5;
    const float* xp = x + ((size_t)b * CIN + c0) * NPIX + n0;
    #pragma unroll
    for (int r = ty; r < 32; r += 8) tile[r][tx] = xp[(size_t)r * NPIX + tx];
    __syncthreads();
    __half* op = g_xt2 + ((size_t)b * NPIX + n0) * KP_X + c0;
    #pragma unroll
    for (int r = ty; r < 32; r += 8) {
        float v = tile[tx][r];
        __half h = __float2half(v);
        __half* orow = op + (size_t)r * KP_X;
        orow[tx] = h; orow[tx + CIN] = h;                     // pattern B
    }
}

// ---------------- BN stats over (B,N) -----------------------------------------
__global__ void __launch_bounds__(256) bn_stats(
    const float* __restrict__ gq, const float* __restrict__ betaq,
    const float* __restrict__ gk, const float* __restrict__ betak)
{
    int o = blockIdx.x;
    int t = threadIdx.x;
    __shared__ float rs[256], rq[256];
    float s = 0.f, sq = 0.f;
    for (int b = 0; b < BATCH; b++) {
        const float* p = g_Z + ((size_t)b * QKV + o) * NPIX;
        for (int i = t; i < NPIX; i += 256) {
            float v = p[i];
            s += v; sq += v * v;
        }
    }
    rs[t] = s; rq[t] = sq;
    __syncthreads();
    for (int st = 128; st > 0; st >>= 1) {
        if (t < st) { rs[t] += rs[t + st]; rq[t] += rq[t + st]; }
        __syncthreads();
    }
    if (t == 0) {
        float cnt = (float)(BATCH * NPIX);
        float mean = rs[0] / cnt;
        float var = rq[0] / cnt - mean * mean;
        float inv = rsqrtf(var + EPSBN);
        float gamma = (o < CK) ? gq[o] : gk[o - CK];
        float beta  = (o < CK) ? betaq[o] : betak[o - CK];
        g_bnA[o] = gamma * inv;
        g_bnB[o] = beta - mean * gamma * inv;
    }
}

// ---------------- BN+ReLU + transpose + split: q pattern B, k pattern A -------
__global__ void __launch_bounds__(256) convert_qk()
{
    __shared__ float tile[32][33];
    int b = blockIdx.z, o0 = blockIdx.y * 32, n0 = blockIdx.x * 32;
    int tx = threadIdx.x & 31, ty = threadIdx.x >> 5;
    #pragma unroll
    for (int r = ty; r < 32; r += 8) {
        int o = o0 + r;
        float z = g_Z[((size_t)b * QKV + o) * NPIX + n0 + tx] * g_bnA[o] + g_bnB[o];
        tile[r][tx] = z > 0.f ? z : 0.f;
    }
    __syncthreads();
    bool isq = (o0 < CK);
    __half* base = isq ? g_qt2 : g_kt2;
    int oc = o0 & (CK - 1);
    __half* op = base + ((size_t)b * NPIX + n0) * KP_QK + oc;
    #pragma unroll
    for (int r = ty; r < 32; r += 8) {
        float v = tile[tx][r];
        __half h, l; hsplit(v, h, l);
        __half* orow = op + (size_t)r * KP_QK;
        if (isq) { orow[tx] = h; orow[tx + CK] = h; }         // B
        else     { orow[tx] = h; orow[tx + CK] = l; }         // A
    }
}

// ---------------- v -> plain fp16 [b][c][m] -----------------------------------
__global__ void __launch_bounds__(256) convert_v()
{
    size_t idx = (size_t)blockIdx.x * 256 + threadIdx.x;   // BATCH*CV*NPIX
    int m = (int)(idx & (NPIX - 1));
    int c = (int)((idx >> 12) & (CV - 1));
    int b = (int)(idx >> 20);
    float v = g_Z[((size_t)b * QKV + 2 * CK + c) * NPIX + m];
    g_v2[idx] = __float2half(v);
}

// ---------------- softmax rows -> plain fp16 P --------------------------------
__global__ void __launch_bounds__(256) softmax_p()
{
    size_t row = blockIdx.x;
    const float* p = g_S + row * NPIX;
    __half* o = g_P2 + row * (size_t)NPIX;
    __shared__ float buf[NPIX];
    __shared__ float red[256];
    int t = threadIdx.x;

    float mx = -1e30f;
    for (int i = t; i < NPIX; i += 256) { float v = p[i]; buf[i] = v; mx = fmaxf(mx, v); }
    red[t] = mx; __syncthreads();
    for (int s = 128; s > 0; s >>= 1) { if (t < s) red[t] = fmaxf(red[t], red[t + s]); __syncthreads(); }
    mx = red[0]; __syncthreads();

    float sum = 0.f;
    for (int i = t; i < NPIX; i += 256) { float e = __expf(buf[i] - mx); buf[i] = e; sum += e; }
    red[t] = sum; __syncthreads();
    for (int s = 128; s > 0; s >>= 1) { if (t < s) red[t] += red[t + s]; __syncthreads(); }
    float inv = 1.f / red[0];
    for (int i = t; i < NPIX; i += 256) o[i] = __float2half(buf[i] * inv);
}

// ---------------- ctx -> split pattern B [b][n][cv'] --------------------------
__global__ void __launch_bounds__(256) convert_ctx()
{
    size_t idx = (size_t)blockIdx.x * 256 + threadIdx.x;   // BATCH*NPIX*CV
    int c = (int)(idx & (CV - 1));
    size_t nrow = idx >> 8;
    float v = g_ctxt[idx];
    __half h = __float2half(v);
    __half* o = g_ctx2 + nrow * KP_CTX;
    o[c] = h; o[c + CV] = h;                                  // pattern B
}

// ---------------- launch ------------------------------------------------------
extern "C" void kernel_launch(void* const* d_in, const int* in_sizes, int n_in,
                              void* d_out, int out_size)
{
    const float* x     = (const float*)d_in[0];
    const float* wq    = (const float*)d_in[1];
    const float* bq    = (const float*)d_in[2];
    const float* gq    = (const float*)d_in[3];
    const float* betaq = (const float*)d_in[4];
    const float* wk    = (const float*)d_in[5];
    const float* bk    = (const float*)d_in[6];
    const float* gk    = (const float*)d_in[7];
    const float* betak = (const float*)d_in[8];
    const float* wv    = (const float*)d_in[9];
    const float* bv    = (const float*)d_in[10];
    const float* wW    = (const float*)d_in[11];
    const float* bW    = (const float*)d_in[12];
    float* out = (float*)d_out;

    void *pwqkv2, *pwW2, *pbias, *pxt2, *pZ, *pqt2, *pkt2, *pv2, *pS, *pP2, *pctxt, *pctx2;
    cudaGetSymbolAddress(&pwqkv2, g_wqkv2);
    cudaGetSymbolAddress(&pwW2, g_wW2);
    cudaGetSymbolAddress(&pbias, g_bias);
    cudaGetSymbolAddress(&pxt2, g_xt2);
    cudaGetSymbolAddress(&pZ, g_Z);
    cudaGetSymbolAddress(&pqt2, g_qt2);
    cudaGetSymbolAddress(&pkt2, g_kt2);
    cudaGetSymbolAddress(&pv2, g_v2);
    cudaGetSymbolAddress(&pS, g_S);
    cudaGetSymbolAddress(&pP2, g_P2);
    cudaGetSymbolAddress(&pctxt, g_ctxt);
    cudaGetSymbolAddress(&pctx2, g_ctx2);

    // 1. prep weights/bias; transpose+split x
    prep_w<<<(QKV * CIN) / 256, 256>>>(wq, bq, wk, bk, wv, bv, wW);
    transpose_x<<<dim3(NPIX / 32, CIN / 32, BATCH), 256>>>(x);

    // 2. qkv projection: Z[o][n] = wqkv2[o,:] . xt2[n,:] + bias   (M=768,N=4096,K=1024)
    gemm_fp16<<<dim3(NPIX / 128, QKV / 128, BATCH), 256>>>(
        (const __half*)pwqkv2, (const __half*)pxt2, (float*)pZ,
        KP_X, KP_X / 32, NPIX,
        0, (size_t)NPIX * KP_X, (size_t)QKV * NPIX,
        (const float*)pbias, nullptr, 0, 1.0f);

    // 3. BN stats; 4. converts
    bn_stats<<<2 * CK, 256>>>(gq, betaq, gk, betak);
    convert_qk<<<dim3(NPIX / 32, (2 * CK) / 32, BATCH), 256>>>();
    convert_v<<<(BATCH * CV * NPIX) / 256, 256>>>();

    // 5. scores: S[n][m] = (1/16) kt2[n,:] . qt2[m,:]   (M=N=4096, K=512)
    gemm_fp16<<<dim3(NPIX / 128, NPIX / 128, BATCH), 256>>>(
        (const __half*)pkt2, (const __half*)pqt2, (float*)pS,
        KP_QK, KP_QK / 32, NPIX,
        (size_t)NPIX * KP_QK, (size_t)NPIX * KP_QK, (size_t)NPIX * NPIX,
        nullptr, nullptr, 0, 0.0625f);

    // 6. softmax + fp16 cast
    softmax_p<<<BATCH * NPIX, 256>>>();

    // 7. ctx^T[n][c] = P2[n,:] . v2[c,:]   (M=4096, N=256, K=4096, plain fp16)
    gemm_fp16<<<dim3(CV / 128, NPIX / 128, BATCH), 256>>>(
        (const __half*)pP2, (const __half*)pv2, (float*)pctxt,
        NPIX, NPIX / 32, CV,
        (size_t)NPIX * NPIX, (size_t)CV * NPIX, (size_t)NPIX * CV,
        nullptr, nullptr, 0, 1.0f);

    // ctx split for final conv
    convert_ctx<<<(BATCH * NPIX * CV) / 256, 256>>>();

    // 8. out[co][n] = wW2[co,:] . ctx2[n,:] + bW[co] + x[co][n]   (M=512,N=4096,K=512)
    gemm_fp16<<<dim3(NPIX / 128, CIN / 128, BATCH), 256>>>(
        (const __half*)pwW2, (const __half*)pctx2, out,
        KP_CTX, KP_CTX / 32, NPIX,
        0, (size_t)NPIX * KP_CTX, (size_t)CIN * NPIX,
        bW, x, (size_t)CIN * NPIX, 1.0f);
}

// round 7
// speedup vs baseline: 4.5154x; 1.3019x over previous
#include <cuda_runtime.h>
#include <cuda_fp16.h>
#include <cstdint>
#include <math.h>

#define BATCH 4
#define CIN   512
#define CK    256
#define CV    256
#define QKV   768
#define NPIX  4096
#define EPSBN 1e-5f

// plain fp16 everywhere: mma.sync accumulates in fp32, so the only error is
// input quantization (~4.9e-4 rel/element) which sqrt-cancels over K.
#define KP_X   512    // = CIN
#define KP_QK  256    // = CK
#define KP_CTX 256    // = CV

// ---------------- scratch globals --------------------------------------------
static __device__ __half g_wqkv2[(size_t)QKV * KP_X];
static __device__ __half g_wW2[(size_t)CIN * KP_CTX];
static __device__ float g_bias[QKV];
static __device__ __half g_xt2[(size_t)BATCH * NPIX * KP_X];
static __device__ float g_Z[(size_t)BATCH * QKV * NPIX];
static __device__ float g_bnA[2 * CK], g_bnB[2 * CK];
static __device__ __half g_qt2[(size_t)BATCH * NPIX * KP_QK];
static __device__ __half g_kt2[(size_t)BATCH * NPIX * KP_QK];
static __device__ __half g_v2[(size_t)BATCH * CV * NPIX];
static __device__ float g_S[(size_t)BATCH * NPIX * NPIX];
static __device__ __half g_P2[(size_t)BATCH * NPIX * NPIX];
static __device__ float g_ctxt[(size_t)BATCH * NPIX * CV];
static __device__ __half g_ctx2[(size_t)BATCH * NPIX * KP_CTX];

// ---------------- helpers ----------------------------------------------------
__device__ __forceinline__ uint32_t smem_u32(const void* p) {
    uint32_t a;
    asm("{ .reg .u64 t; cvta.to.shared.u64 t, %1; cvt.u32.u64 %0, t; }" : "=r"(a) : "l"(p));
    return a;
}
__device__ __forceinline__ void cp16(uint32_t dst, const void* src) {
    asm volatile("cp.async.cg.shared.global [%0], [%1], 16;" :: "r"(dst), "l"(src));
}
__device__ __forceinline__ void cp_commit() { asm volatile("cp.async.commit_group;" ::: "memory"); }
__device__ __forceinline__ void cp_wait1()  { asm volatile("cp.async.wait_group 1;" ::: "memory"); }

__device__ __forceinline__ uint32_t lds32(uint32_t a) {
    uint32_t v;
    asm volatile("ld.shared.b32 %0, [%1];" : "=r"(v) : "r"(a));
    return v;
}
__device__ __forceinline__ void mma16816(float* d, const uint32_t* a, uint32_t b0, uint32_t b1) {
    asm volatile(
        "mma.sync.aligned.m16n8k16.row.col.f32.f16.f16.f32 "
        "{%0,%1,%2,%3}, {%4,%5,%6,%7}, {%8,%9}, {%0,%1,%2,%3};"
        : "+f"(d[0]), "+f"(d[1]), "+f"(d[2]), "+f"(d[3])
        : "r"(a[0]), "r"(a[1]), "r"(a[2]), "r"(a[3]), "r"(b0), "r"(b1));
}

// ---------------- generic fp16 NT GEMM on HMMA --------------------------------
// C[i,j] = alpha * sum_k A[i,k]*B[j,k] (+bias[i]) (+resid[i,j]); fp32 out.
// A: M x K row-major fp16, B: N x K row-major fp16, K % 32 == 0.
// CTA tile 128x128, BK=32, 8 warps (4x2), warp tile 32x64.
#define ROWB 80            // 64B data + 16B pad per smem row
#define OPB  10240
#define STG  20480

__global__ void __launch_bounds__(256, 2)
gemm_fp16(const __half* __restrict__ A, const __half* __restrict__ B,
          float* __restrict__ C, int K, int nit, int ldc,
          size_t sA, size_t sB, size_t sC,
          const float* __restrict__ bias, const float* __restrict__ resid, size_t sR,
          float alpha)
{
    __shared__ __align__(16) char smem[2 * STG];
    uint32_t sb = smem_u32(smem);
    int tid = threadIdx.x, wid = tid >> 5, lane = tid & 31;
    int bz = blockIdx.z;
    int i0 = blockIdx.y * 128;
    int j0 = blockIdx.x * 128;

    const char* ap = (const char*)(A + sA * bz);
    const char* bp = (const char*)(B + sB * bz);

    const char* asrc[2]; uint32_t adst[2];
    const char* bsrc[2]; uint32_t bdst[2];
    #pragma unroll
    for (int jj = 0; jj < 2; jj++) {
        int idx = tid + 256 * jj, row = idx >> 2, seg = idx & 3;
        asrc[jj] = ap + ((size_t)(i0 + row) * K) * 2 + seg * 16;
        adst[jj] = sb + row * ROWB + seg * 16;
        bsrc[jj] = bp + ((size_t)(j0 + row) * K) * 2 + seg * 16;
        bdst[jj] = sb + OPB + row * ROWB + seg * 16;
    }

    int g = lane >> 2, tg = lane & 3;
    int mw = wid >> 1, nw = wid & 1;
    uint32_t aB = sb + (mw * 32 + g) * ROWB + tg * 4;
    uint32_t bB = sb + OPB + (nw * 64 + g) * ROWB + tg * 4;

    float acc[2][8][4];
    #pragma unroll
    for (int t = 0; t < 2; t++)
        #pragma unroll
        for (int j = 0; j < 8; j++)
            #pragma unroll
            for (int c = 0; c < 4; c++) acc[t][j][c] = 0.f;

    #pragma unroll
    for (int jj = 0; jj < 2; jj++) { cp16(adst[jj], asrc[jj]); cp16(bdst[jj], bsrc[jj]); }
    cp_commit();

    for (int it = 0; it < nit; it++) {
        if (it + 1 < nit) {
            size_t ko = (size_t)(it + 1) * 64;
            uint32_t so = ((it + 1) & 1) * STG;
            #pragma unroll
            for (int jj = 0; jj < 2; jj++) {
                cp16(adst[jj] + so, asrc[jj] + ko);
                cp16(bdst[jj] + so, bsrc[jj] + ko);
            }
        }
        cp_commit();
        cp_wait1();
        __syncthreads();

        uint32_t so = (it & 1) * STG;
        #pragma unroll
        for (int k16 = 0; k16 < 2; k16++) {
            uint32_t kb = k16 * 32;
            uint32_t a[2][4];
            #pragma unroll
            for (int t = 0; t < 2; t++) {
                uint32_t base = aB + so + t * (16 * ROWB) + kb;
                a[t][0] = lds32(base);
                a[t][1] = lds32(base + 8 * ROWB);
                a[t][2] = lds32(base + 16);
                a[t][3] = lds32(base + 8 * ROWB + 16);
            }
            #pragma unroll
            for (int j = 0; j < 8; j++) {
                uint32_t base = bB + so + j * (8 * ROWB) + kb;
                uint32_t b0 = lds32(base);
                uint32_t b1 = lds32(base + 16);
                mma16816(acc[0][j], a[0], b0, b1);
                mma16816(acc[1][j], a[1], b0, b1);
            }
        }
        __syncthreads();
    }

    float* cb = C + sC * bz;
    const float* rb = resid ? resid + sR * bz : nullptr;
    #pragma unroll
    for (int t = 0; t < 2; t++) {
        int r0 = i0 + mw * 32 + t * 16 + g;
        int r1 = r0 + 8;
        float bi0 = bias ? bias[r0] : 0.f;
        float bi1 = bias ? bias[r1] : 0.f;
        #pragma unroll
        for (int j = 0; j < 8; j++) {
            int c = j0 + nw * 64 + j * 8 + tg * 2;
            float v0 = acc[t][j][0] * alpha + bi0;
            float v1 = acc[t][j][1] * alpha + bi0;
            float v2 = acc[t][j][2] * alpha + bi1;
            float v3 = acc[t][j][3] * alpha + bi1;
            if (rb) {
                float2 x0 = *(const float2*)(rb + (size_t)r0 * ldc + c);
                float2 x1 = *(const float2*)(rb + (size_t)r1 * ldc + c);
                v0 += x0.x; v1 += x0.y; v2 += x1.x; v3 += x1.y;
            }
            *(float2*)(cb + (size_t)r0 * ldc + c) = make_float2(v0, v1);
            *(float2*)(cb + (size_t)r1 * ldc + c) = make_float2(v2, v3);
        }
    }
}

// ---------------- prep: weights -> fp16 + bias concat -------------------------
__global__ void __launch_bounds__(256) prep_w(
    const float* __restrict__ wq, const float* __restrict__ bq,
    const float* __restrict__ wk, const float* __restrict__ bk,
    const float* __restrict__ wv, const float* __restrict__ bv,
    const float* __restrict__ wW)
{
    int idx = blockIdx.x * 256 + threadIdx.x;   // < QKV*CIN
    {
        int o = idx / CIN, c = idx % CIN;
        float v = (o < CK) ? wq[o * CIN + c] : (o < 2 * CK) ? wk[(o - CK) * CIN + c]
                                                            : wv[(o - 2 * CK) * CIN + c];
        g_wqkv2[(size_t)o * KP_X + c] = __float2half(v);
    }
    if (idx < CIN * CV) {
        int co = idx / CV, cv = idx % CV;
        g_wW2[(size_t)co * KP_CTX + cv] = __float2half(wW[co * CV + cv]);
    }
    if (idx < QKV)
        g_bias[idx] = (idx < CK) ? bq[idx] : (idx < 2 * CK) ? bk[idx - CK] : bv[idx - 2 * CK];
}

// ---------------- x transpose -> fp16 [b][n][c] -------------------------------
__global__ void __launch_bounds__(256) transpose_x(const float* __restrict__ x)
{
    __shared__ float tile[32][33];
    int b = blockIdx.z, c0 = blockIdx.y * 32, n0 = blockIdx.x * 32;
    int tx = threadIdx.x & 31, ty = threadIdx.x >> 5;
    const float* xp = x + ((size_t)b * CIN + c0) * NPIX + n0;
    #pragma unroll
    for (int r = ty; r < 32; r += 8) tile[r][tx] = xp[(size_t)r * NPIX + tx];
    __syncthreads();
    __half* op = g_xt2 + ((size_t)b * NPIX + n0) * KP_X + c0;
    #pragma unroll
    for (int r = ty; r < 32; r += 8)
        op[(size_t)r * KP_X + tx] = __float2half(tile[tx][r]);
}

// ---------------- BN stats over (B,N) -----------------------------------------
__global__ void __launch_bounds__(256) bn_stats(
    const float* __restrict__ gq, const float* __restrict__ betaq,
    const float* __restrict__ gk, const float* __restrict__ betak)
{
    int o = blockIdx.x;
    int t = threadIdx.x;
    __shared__ float rs[256], rq[256];
    float s = 0.f, sq = 0.f;
    for (int b = 0; b < BATCH; b++) {
        const float* p = g_Z + ((size_t)b * QKV + o) * NPIX;
        for (int i = t; i < NPIX; i += 256) {
            float v = p[i];
            s += v; sq += v * v;
        }
    }
    rs[t] = s; rq[t] = sq;
    __syncthreads();
    for (int st = 128; st > 0; st >>= 1) {
        if (t < st) { rs[t] += rs[t + st]; rq[t] += rq[t + st]; }
        __syncthreads();
    }
    if (t == 0) {
        float cnt = (float)(BATCH * NPIX);
        float mean = rs[0] / cnt;
        float var = rq[0] / cnt - mean * mean;
        float inv = rsqrtf(var + EPSBN);
        float gamma = (o < CK) ? gq[o] : gk[o - CK];
        float beta  = (o < CK) ? betaq[o] : betak[o - CK];
        g_bnA[o] = gamma * inv;
        g_bnB[o] = beta - mean * gamma * inv;
    }
}

// ---------------- BN+ReLU + transpose -> qt2 / kt2 (fp16) ---------------------
__global__ void __launch_bounds__(256) convert_qk()
{
    __shared__ float tile[32][33];
    int b = blockIdx.z, o0 = blockIdx.y * 32, n0 = blockIdx.x * 32;
    int tx = threadIdx.x & 31, ty = threadIdx.x >> 5;
    #pragma unroll
    for (int r = ty; r < 32; r += 8) {
        int o = o0 + r;
        float z = g_Z[((size_t)b * QKV + o) * NPIX + n0 + tx] * g_bnA[o] + g_bnB[o];
        tile[r][tx] = z > 0.f ? z : 0.f;
    }
    __syncthreads();
    bool isq = (o0 < CK);
    __half* base = isq ? g_qt2 : g_kt2;
    int oc = o0 & (CK - 1);
    __half* op = base + ((size_t)b * NPIX + n0) * KP_QK + oc;
    #pragma unroll
    for (int r = ty; r < 32; r += 8)
        op[(size_t)r * KP_QK + tx] = __float2half(tile[tx][r]);
}

// ---------------- v -> plain fp16 [b][c][m] -----------------------------------
__global__ void __launch_bounds__(256) convert_v()
{
    size_t idx = (size_t)blockIdx.x * 256 + threadIdx.x;   // BATCH*CV*NPIX
    int m = (int)(idx & (NPIX - 1));
    int c = (int)((idx >> 12) & (CV - 1));
    int b = (int)(idx >> 20);
    float v = g_Z[((size_t)b * QKV + 2 * CK + c) * NPIX + m];
    g_v2[idx] = __float2half(v);
}

// ---------------- softmax rows -> plain fp16 P --------------------------------
__global__ void __launch_bounds__(256) softmax_p()
{
    size_t row = blockIdx.x;
    const float* p = g_S + row * NPIX;
    __half* o = g_P2 + row * (size_t)NPIX;
    __shared__ float buf[NPIX];
    __shared__ float red[256];
    int t = threadIdx.x;

    float mx = -1e30f;
    for (int i = t; i < NPIX; i += 256) { float v = p[i]; buf[i] = v; mx = fmaxf(mx, v); }
    red[t] = mx; __syncthreads();
    for (int s = 128; s > 0; s >>= 1) { if (t < s) red[t] = fmaxf(red[t], red[t + s]); __syncthreads(); }
    mx = red[0]; __syncthreads();

    float sum = 0.f;
    for (int i = t; i < NPIX; i += 256) { float e = __expf(buf[i] - mx); buf[i] = e; sum += e; }
    red[t] = sum; __syncthreads();
    for (int s = 128; s > 0; s >>= 1) { if (t < s) red[t] += red[t + s]; __syncthreads(); }
    float inv = 1.f / red[0];
    for (int i = t; i < NPIX; i += 256) o[i] = __float2half(buf[i] * inv);
}

// ---------------- ctx -> fp16 [b][n][cv] --------------------------------------
__global__ void __launch_bounds__(256) convert_ctx()
{
    size_t idx = (size_t)blockIdx.x * 256 + threadIdx.x;   // BATCH*NPIX*CV
    g_ctx2[idx] = __float2half(g_ctxt[idx]);
}

// ---------------- launch ------------------------------------------------------
extern "C" void kernel_launch(void* const* d_in, const int* in_sizes, int n_in,
                              void* d_out, int out_size)
{
    const float* x     = (const float*)d_in[0];
    const float* wq    = (const float*)d_in[1];
    const float* bq    = (const float*)d_in[2];
    const float* gq    = (const float*)d_in[3];
    const float* betaq = (const float*)d_in[4];
    const float* wk    = (const float*)d_in[5];
    const float* bk    = (const float*)d_in[6];
    const float* gk    = (const float*)d_in[7];
    const float* betak = (const float*)d_in[8];
    const float* wv    = (const float*)d_in[9];
    const float* bv    = (const float*)d_in[10];
    const float* wW    = (const float*)d_in[11];
    const float* bW    = (const float*)d_in[12];
    float* out = (float*)d_out;

    void *pwqkv2, *pwW2, *pbias, *pxt2, *pZ, *pqt2, *pkt2, *pv2, *pS, *pP2, *pctxt, *pctx2;
    cudaGetSymbolAddress(&pwqkv2, g_wqkv2);
    cudaGetSymbolAddress(&pwW2, g_wW2);
    cudaGetSymbolAddress(&pbias, g_bias);
    cudaGetSymbolAddress(&pxt2, g_xt2);
    cudaGetSymbolAddress(&pZ, g_Z);
    cudaGetSymbolAddress(&pqt2, g_qt2);
    cudaGetSymbolAddress(&pkt2, g_kt2);
    cudaGetSymbolAddress(&pv2, g_v2);
    cudaGetSymbolAddress(&pS, g_S);
    cudaGetSymbolAddress(&pP2, g_P2);
    cudaGetSymbolAddress(&pctxt, g_ctxt);
    cudaGetSymbolAddress(&pctx2, g_ctx2);

    // 1. prep weights/bias; transpose x
    prep_w<<<(QKV * CIN) / 256, 256>>>(wq, bq, wk, bk, wv, bv, wW);
    transpose_x<<<dim3(NPIX / 32, CIN / 32, BATCH), 256>>>(x);

    // 2. qkv projection: Z[o][n] = wqkv2[o,:] . xt2[n,:] + bias   (M=768,N=4096,K=512)
    gemm_fp16<<<dim3(NPIX / 128, QKV / 128, BATCH), 256>>>(
        (const __half*)pwqkv2, (const __half*)pxt2, (float*)pZ,
        KP_X, KP_X / 32, NPIX,
        0, (size_t)NPIX * KP_X, (size_t)QKV * NPIX,
        (const float*)pbias, nullptr, 0, 1.0f);

    // 3. BN stats; 4. converts
    bn_stats<<<2 * CK, 256>>>(gq, betaq, gk, betak);
    convert_qk<<<dim3(NPIX / 32, (2 * CK) / 32, BATCH), 256>>>();
    convert_v<<<(BATCH * CV * NPIX) / 256, 256>>>();

    // 5. scores: S[n][m] = (1/16) kt2[n,:] . qt2[m,:]   (M=N=4096, K=256)
    gemm_fp16<<<dim3(NPIX / 128, NPIX / 128, BATCH), 256>>>(
        (const __half*)pkt2, (const __half*)pqt2, (float*)pS,
        KP_QK, KP_QK / 32, NPIX,
        (size_t)NPIX * KP_QK, (size_t)NPIX * KP_QK, (size_t)NPIX * NPIX,
        nullptr, nullptr, 0, 0.0625f);

    // 6. softmax + fp16 cast
    softmax_p<<<BATCH * NPIX, 256>>>();

    // 7. ctx^T[n][c] = P2[n,:] . v2[c,:]   (M=4096, N=256, K=4096)
    gemm_fp16<<<dim3(CV / 128, NPIX / 128, BATCH), 256>>>(
        (const __half*)pP2, (const __half*)pv2, (float*)pctxt,
        NPIX, NPIX / 32, CV,
        (size_t)NPIX * NPIX, (size_t)CV * NPIX, (size_t)NPIX * CV,
        nullptr, nullptr, 0, 1.0f);

    // ctx -> fp16 for final conv
    convert_ctx<<<(BATCH * NPIX * CV) / 256, 256>>>();

    // 8. out[co][n] = wW2[co,:] . ctx2[n,:] + bW[co] + x[co][n]   (M=512,N=4096,K=256)
    gemm_fp16<<<dim3(NPIX / 128, CIN / 128, BATCH), 256>>>(
        (const __half*)pwW2, (const __half*)pctx2, out,
        KP_CTX, KP_CTX / 32, NPIX,
        0, (size_t)NPIX * KP_CTX, (size_t)CIN * NPIX,
        bW, x, (size_t)CIN * NPIX, 1.0f);
}

// round 8
// speedup vs baseline: 6.9164x; 1.5317x over previous
#include <cuda_runtime.h>
#include <cuda_fp16.h>
#include <cstdint>
#include <math.h>

#define BATCH 4
#define CIN   512
#define CK    256
#define CV    256
#define QKV   768
#define NPIX  4096
#define EPSBN 1e-5f

#define KP_X   512    // = CIN
#define KP_QK  256    // = CK
#define KP_CTX 256    // = CV

// ---------------- scratch globals --------------------------------------------
static __device__ __half g_wqkv2[(size_t)QKV * KP_X];
static __device__ __half g_wW2[(size_t)CIN * KP_CTX];
static __device__ float g_bias[QKV];
static __device__ __half g_xt2[(size_t)BATCH * NPIX * KP_X];
static __device__ float g_Z[(size_t)BATCH * QKV * NPIX];
static __device__ float g_bnA[2 * CK], g_bnB[2 * CK];
static __device__ __half g_qt2[(size_t)BATCH * NPIX * KP_QK];   // [b][m][k]
static __device__ __half g_kt2[(size_t)BATCH * NPIX * KP_QK];   // [b][n][k]
static __device__ __half g_v2[(size_t)BATCH * CV * NPIX];       // [b][c][m]
static __device__ __half g_ctx2[(size_t)BATCH * NPIX * KP_CTX]; // [b][n][c]

// ---------------- helpers ----------------------------------------------------
__device__ __forceinline__ uint32_t smem_u32(const void* p) {
    uint32_t a;
    asm("{ .reg .u64 t; cvta.to.shared.u64 t, %1; cvt.u32.u64 %0, t; }" : "=r"(a) : "l"(p));
    return a;
}
__device__ __forceinline__ void cp16(uint32_t dst, const void* src) {
    asm volatile("cp.async.cg.shared.global [%0], [%1], 16;" :: "r"(dst), "l"(src));
}
__device__ __forceinline__ void cp_commit() { asm volatile("cp.async.commit_group;" ::: "memory"); }
__device__ __forceinline__ void cp_wait1()  { asm volatile("cp.async.wait_group 1;" ::: "memory"); }

__device__ __forceinline__ uint32_t lds32(uint32_t a) {
    uint32_t v;
    asm volatile("ld.shared.b32 %0, [%1];" : "=r"(v) : "r"(a));
    return v;
}
__device__ __forceinline__ void mma16816(float* d, const uint32_t* a, uint32_t b0, uint32_t b1) {
    asm volatile(
        "mma.sync.aligned.m16n8k16.row.col.f32.f16.f16.f32 "
        "{%0,%1,%2,%3}, {%4,%5,%6,%7}, {%8,%9}, {%0,%1,%2,%3};"
        : "+f"(d[0]), "+f"(d[1]), "+f"(d[2]), "+f"(d[3])
        : "r"(a[0]), "r"(a[1]), "r"(a[2]), "r"(a[3]), "r"(b0), "r"(b1));
}
__device__ __forceinline__ uint32_t packh2(float lo, float hi) {
    __half2 h = __floats2half2_rn(lo, hi);
    return *(uint32_t*)&h;
}

// ---------------- generic fp16 NT GEMM on HMMA --------------------------------
#define ROWB 80
#define OPB  10240
#define STG  20480

__global__ void __launch_bounds__(256, 2)
gemm_fp16(const __half* __restrict__ A, const __half* __restrict__ B,
          float* __restrict__ C, int K, int nit, int ldc,
          size_t sA, size_t sB, size_t sC,
          const float* __restrict__ bias, const float* __restrict__ resid, size_t sR,
          float alpha)
{
    __shared__ __align__(16) char smem[2 * STG];
    uint32_t sb = smem_u32(smem);
    int tid = threadIdx.x, wid = tid >> 5, lane = tid & 31;
    int bz = blockIdx.z;
    int i0 = blockIdx.y * 128;
    int j0 = blockIdx.x * 128;

    const char* ap = (const char*)(A + sA * bz);
    const char* bp = (const char*)(B + sB * bz);

    const char* asrc[2]; uint32_t adst[2];
    const char* bsrc[2]; uint32_t bdst[2];
    #pragma unroll
    for (int jj = 0; jj < 2; jj++) {
        int idx = tid + 256 * jj, row = idx >> 2, seg = idx & 3;
        asrc[jj] = ap + ((size_t)(i0 + row) * K) * 2 + seg * 16;
        adst[jj] = sb + row * ROWB + seg * 16;
        bsrc[jj] = bp + ((size_t)(j0 + row) * K) * 2 + seg * 16;
        bdst[jj] = sb + OPB + row * ROWB + seg * 16;
    }

    int g = lane >> 2, tg = lane & 3;
    int mw = wid >> 1, nw = wid & 1;
    uint32_t aB = sb + (mw * 32 + g) * ROWB + tg * 4;
    uint32_t bB = sb + OPB + (nw * 64 + g) * ROWB + tg * 4;

    float acc[2][8][4];
    #pragma unroll
    for (int t = 0; t < 2; t++)
        #pragma unroll
        for (int j = 0; j < 8; j++)
            #pragma unroll
            for (int c = 0; c < 4; c++) acc[t][j][c] = 0.f;

    #pragma unroll
    for (int jj = 0; jj < 2; jj++) { cp16(adst[jj], asrc[jj]); cp16(bdst[jj], bsrc[jj]); }
    cp_commit();

    for (int it = 0; it < nit; it++) {
        if (it + 1 < nit) {
            size_t ko = (size_t)(it + 1) * 64;
            uint32_t so = ((it + 1) & 1) * STG;
            #pragma unroll
            for (int jj = 0; jj < 2; jj++) {
                cp16(adst[jj] + so, asrc[jj] + ko);
                cp16(bdst[jj] + so, bsrc[jj] + ko);
            }
        }
        cp_commit();
        cp_wait1();
        __syncthreads();

        uint32_t so = (it & 1) * STG;
        #pragma unroll
        for (int k16 = 0; k16 < 2; k16++) {
            uint32_t kb = k16 * 32;
            uint32_t a[2][4];
            #pragma unroll
            for (int t = 0; t < 2; t++) {
                uint32_t base = aB + so + t * (16 * ROWB) + kb;
                a[t][0] = lds32(base);
                a[t][1] = lds32(base + 8 * ROWB);
                a[t][2] = lds32(base + 16);
                a[t][3] = lds32(base + 8 * ROWB + 16);
            }
            #pragma unroll
            for (int j = 0; j < 8; j++) {
                uint32_t base = bB + so + j * (8 * ROWB) + kb;
                uint32_t b0 = lds32(base);
                uint32_t b1 = lds32(base + 16);
                mma16816(acc[0][j], a[0], b0, b1);
                mma16816(acc[1][j], a[1], b0, b1);
            }
        }
        __syncthreads();
    }

    float* cb = C + sC * bz;
    const float* rb = resid ? resid + sR * bz : nullptr;
    #pragma unroll
    for (int t = 0; t < 2; t++) {
        int r0 = i0 + mw * 32 + t * 16 + g;
        int r1 = r0 + 8;
        float bi0 = bias ? bias[r0] : 0.f;
        float bi1 = bias ? bias[r1] : 0.f;
        #pragma unroll
        for (int j = 0; j < 8; j++) {
            int c = j0 + nw * 64 + j * 8 + tg * 2;
            float v0 = acc[t][j][0] * alpha + bi0;
            float v1 = acc[t][j][1] * alpha + bi0;
            float v2 = acc[t][j][2] * alpha + bi1;
            float v3 = acc[t][j][3] * alpha + bi1;
            if (rb) {
                float2 x0 = *(const float2*)(rb + (size_t)r0 * ldc + c);
                float2 x1 = *(const float2*)(rb + (size_t)r1 * ldc + c);
                v0 += x0.x; v1 += x0.y; v2 += x1.x; v3 += x1.y;
            }
            *(float2*)(cb + (size_t)r0 * ldc + c) = make_float2(v0, v1);
            *(float2*)(cb + (size_t)r1 * ldc + c) = make_float2(v2, v3);
        }
    }
}

// ---------------- flash attention: S=K.Q^T -> online softmax -> O=P.V^T -------
// Grid (NPIX/128, BATCH); CTA: 128 n-rows, loop m in tiles of 64.
// Warp w owns n rows [w*16, w*16+16). O acc 16x256 fp32/warp.
#define KROW 528                 // 256 fp16 = 512B + 16 pad
#define VROW 144                 // 64 fp16 = 128B + 16 pad
#define SM_Q 67584               // after K tile (128*528)
#define QSTG 33792               // 64*528
#define SM_V (67584 + 2*33792)   // 135168
#define VSTG 36864               // 256*144
#define FL_SMEM (135168 + 2*36864)  // 208896

__global__ void __launch_bounds__(256, 1)
flash_attn(const __half* __restrict__ Kt, const __half* __restrict__ Qt,
           const __half* __restrict__ V, __half* __restrict__ ctx2)
{
    extern __shared__ __align__(16) char smem[];
    uint32_t sb = smem_u32(smem);
    int tid = threadIdx.x, wid = tid >> 5, lane = tid & 31;
    int g = lane >> 2, tg = lane & 3;
    int b = blockIdx.y;
    int n0 = blockIdx.x * 128;

    const char* kp = (const char*)(Kt + ((size_t)b * NPIX + n0) * CK);
    const char* qp = (const char*)(Qt + (size_t)b * NPIX * CK);
    const char* vp = (const char*)(V + (size_t)b * CV * NPIX);

    // K tile: 128 rows x 512B
    #pragma unroll
    for (int j = 0; j < 16; j++) {
        int idx = tid + 256 * j, row = idx >> 5, seg = idx & 31;
        cp16(sb + row * KROW + seg * 16, kp + (size_t)row * 512 + seg * 16);
    }
    // Q,V stage 0 (m-tile 0)
    #pragma unroll
    for (int j = 0; j < 8; j++) {
        int idx = tid + 256 * j;
        int qrow = idx >> 5, qseg = idx & 31;
        cp16(sb + SM_Q + qrow * KROW + qseg * 16, qp + (size_t)qrow * 512 + qseg * 16);
        int vrow = idx >> 3, vseg = idx & 7;
        cp16(sb + SM_V + vrow * VROW + vseg * 16, vp + ((size_t)vrow * NPIX) * 2 + vseg * 16);
    }
    cp_commit();

    float o[32][4];
    #pragma unroll
    for (int j = 0; j < 32; j++)
        #pragma unroll
        for (int c = 0; c < 4; c++) o[j][c] = 0.f;
    float m0 = -1e30f, m8 = -1e30f, l0 = 0.f, l8 = 0.f;

    uint32_t kbase = sb + (wid * 16 + g) * KROW + tg * 4;

    for (int it = 0; it < NPIX / 64; it++) {
        if (it + 1 < NPIX / 64) {
            int st = (it + 1) & 1;
            size_t mo = (size_t)(it + 1) * 64;
            #pragma unroll
            for (int j = 0; j < 8; j++) {
                int idx = tid + 256 * j;
                int qrow = idx >> 5, qseg = idx & 31;
                cp16(sb + SM_Q + st * QSTG + qrow * KROW + qseg * 16,
                     qp + ((size_t)(mo + qrow)) * 512 + qseg * 16);
                int vrow = idx >> 3, vseg = idx & 7;
                cp16(sb + SM_V + st * VSTG + vrow * VROW + vseg * 16,
                     vp + ((size_t)vrow * NPIX + mo) * 2 + vseg * 16);
            }
        }
        cp_commit();
        cp_wait1();
        __syncthreads();

        int st = it & 1;
        uint32_t qb0 = sb + SM_Q + st * QSTG + g * KROW + tg * 4;
        uint32_t vb0 = sb + SM_V + st * VSTG + g * VROW + tg * 4;

        // ---- gemm1: S[16n x 64m] per warp, K'=256 ----
        float s[8][4];
        #pragma unroll
        for (int j = 0; j < 8; j++)
            #pragma unroll
            for (int c = 0; c < 4; c++) s[j][c] = 0.f;
        #pragma unroll
        for (int k16 = 0; k16 < 16; k16++) {
            uint32_t ab = kbase + k16 * 32;
            uint32_t a[4];
            a[0] = lds32(ab); a[1] = lds32(ab + 8 * KROW);
            a[2] = lds32(ab + 16); a[3] = lds32(ab + 8 * KROW + 16);
            #pragma unroll
            for (int j = 0; j < 8; j++) {
                uint32_t bb = qb0 + j * (8 * KROW) + k16 * 32;
                mma16816(s[j], a, lds32(bb), lds32(bb + 16));
            }
        }
        // scale
        #pragma unroll
        for (int j = 0; j < 8; j++)
            #pragma unroll
            for (int c = 0; c < 4; c++) s[j][c] *= 0.0625f;

        // ---- online softmax ----
        float mx0 = -1e30f, mx8 = -1e30f;
        #pragma unroll
        for (int j = 0; j < 8; j++) {
            mx0 = fmaxf(mx0, fmaxf(s[j][0], s[j][1]));
            mx8 = fmaxf(mx8, fmaxf(s[j][2], s[j][3]));
        }
        mx0 = fmaxf(mx0, __shfl_xor_sync(0xffffffffu, mx0, 1));
        mx0 = fmaxf(mx0, __shfl_xor_sync(0xffffffffu, mx0, 2));
        mx8 = fmaxf(mx8, __shfl_xor_sync(0xffffffffu, mx8, 1));
        mx8 = fmaxf(mx8, __shfl_xor_sync(0xffffffffu, mx8, 2));
        float nm0 = fmaxf(m0, mx0), nm8 = fmaxf(m8, mx8);
        float sc0 = __expf(m0 - nm0), sc8 = __expf(m8 - nm8);
        m0 = nm0; m8 = nm8;

        float sum0 = 0.f, sum8 = 0.f;
        uint32_t pa[8][2];
        #pragma unroll
        for (int j = 0; j < 8; j++) {
            float p0 = __expf(s[j][0] - m0);
            float p1 = __expf(s[j][1] - m0);
            float p2 = __expf(s[j][2] - m8);
            float p3 = __expf(s[j][3] - m8);
            sum0 += p0 + p1; sum8 += p2 + p3;
            pa[j][0] = packh2(p0, p1);
            pa[j][1] = packh2(p2, p3);
        }
        sum0 += __shfl_xor_sync(0xffffffffu, sum0, 1);
        sum0 += __shfl_xor_sync(0xffffffffu, sum0, 2);
        sum8 += __shfl_xor_sync(0xffffffffu, sum8, 1);
        sum8 += __shfl_xor_sync(0xffffffffu, sum8, 2);
        l0 = l0 * sc0 + sum0;
        l8 = l8 * sc8 + sum8;

        // rescale O
        #pragma unroll
        for (int j = 0; j < 32; j++) {
            o[j][0] *= sc0; o[j][1] *= sc0;
            o[j][2] *= sc8; o[j][3] *= sc8;
        }

        // ---- gemm2: O[16n x 256c] += P[16n x 64m] . V[256c x 64m]^T ----
        #pragma unroll
        for (int t = 0; t < 4; t++) {
            uint32_t a2[4] = { pa[2 * t][0], pa[2 * t][1], pa[2 * t + 1][0], pa[2 * t + 1][1] };
            #pragma unroll
            for (int j2 = 0; j2 < 32; j2++) {
                uint32_t bb = vb0 + j2 * (8 * VROW) + t * 32;
                mma16816(o[j2], a2, lds32(bb), lds32(bb + 16));
            }
        }
        __syncthreads();
    }

    // epilogue: O /= l, write fp16 ctx2 [b][n][c]
    float i0 = 1.f / l0, i8 = 1.f / l8;
    int nrow = n0 + wid * 16 + g;
    __half2* out0 = (__half2*)(ctx2 + ((size_t)b * NPIX + nrow) * CV);
    __half2* out8 = (__half2*)(ctx2 + ((size_t)b * NPIX + nrow + 8) * CV);
    #pragma unroll
    for (int j2 = 0; j2 < 32; j2++) {
        int cp_ = 4 * j2 + tg;   // half2 index: col = 8*j2 + tg*2
        out0[cp_] = __floats2half2_rn(o[j2][0] * i0, o[j2][1] * i0);
        out8[cp_] = __floats2half2_rn(o[j2][2] * i8, o[j2][3] * i8);
    }
}

// ---------------- prep: weights -> fp16 + bias concat -------------------------
__global__ void __launch_bounds__(256) prep_w(
    const float* __restrict__ wq, const float* __restrict__ bq,
    const float* __restrict__ wk, const float* __restrict__ bk,
    const float* __restrict__ wv, const float* __restrict__ bv,
    const float* __restrict__ wW)
{
    int idx = blockIdx.x * 256 + threadIdx.x;
    {
        int o = idx / CIN, c = idx % CIN;
        float v = (o < CK) ? wq[o * CIN + c] : (o < 2 * CK) ? wk[(o - CK) * CIN + c]
                                                            : wv[(o - 2 * CK) * CIN + c];
        g_wqkv2[(size_t)o * KP_X + c] = __float2half(v);
    }
    if (idx < CIN * CV) {
        int co = idx / CV, cv = idx % CV;
        g_wW2[(size_t)co * KP_CTX + cv] = __float2half(wW[co * CV + cv]);
    }
    if (idx < QKV)
        g_bias[idx] = (idx < CK) ? bq[idx] : (idx < 2 * CK) ? bk[idx - CK] : bv[idx - 2 * CK];
}

// ---------------- x transpose -> fp16 [b][n][c] -------------------------------
__global__ void __launch_bounds__(256) transpose_x(const float* __restrict__ x)
{
    __shared__ float tile[32][33];
    int b = blockIdx.z, c0 = blockIdx.y * 32, n0 = blockIdx.x * 32;
    int tx = threadIdx.x & 31, ty = threadIdx.x >> 5;
    const float* xp = x + ((size_t)b * CIN + c0) * NPIX + n0;
    #pragma unroll
    for (int r = ty; r < 32; r += 8) tile[r][tx] = xp[(size_t)r * NPIX + tx];
    __syncthreads();
    __half* op = g_xt2 + ((size_t)b * NPIX + n0) * KP_X + c0;
    #pragma unroll
    for (int r = ty; r < 32; r += 8)
        op[(size_t)r * KP_X + tx] = __float2half(tile[tx][r]);
}

// ---------------- BN stats over (B,N) -----------------------------------------
__global__ void __launch_bounds__(256) bn_stats(
    const float* __restrict__ gq, const float* __restrict__ betaq,
    const float* __restrict__ gk, const float* __restrict__ betak)
{
    int o = blockIdx.x;
    int t = threadIdx.x;
    __shared__ float rs[256], rq[256];
    float s = 0.f, sq = 0.f;
    for (int b = 0; b < BATCH; b++) {
        const float* p = g_Z + ((size_t)b * QKV + o) * NPIX;
        for (int i = t; i < NPIX; i += 256) {
            float v = p[i];
            s += v; sq += v * v;
        }
    }
    rs[t] = s; rq[t] = sq;
    __syncthreads();
    for (int st = 128; st > 0; st >>= 1) {
        if (t < st) { rs[t] += rs[t + st]; rq[t] += rq[t + st]; }
        __syncthreads();
    }
    if (t == 0) {
        float cnt = (float)(BATCH * NPIX);
        float mean = rs[0] / cnt;
        float var = rq[0] / cnt - mean * mean;
        float inv = rsqrtf(var + EPSBN);
        float gamma = (o < CK) ? gq[o] : gk[o - CK];
        float beta  = (o < CK) ? betaq[o] : betak[o - CK];
        g_bnA[o] = gamma * inv;
        g_bnB[o] = beta - mean * gamma * inv;
    }
}

// ---------------- BN+ReLU + transpose -> qt2 / kt2 (fp16) ---------------------
__global__ void __launch_bounds__(256) convert_qk()
{
    __shared__ float tile[32][33];
    int b = blockIdx.z, o0 = blockIdx.y * 32, n0 = blockIdx.x * 32;
    int tx = threadIdx.x & 31, ty = threadIdx.x >> 5;
    #pragma unroll
    for (int r = ty; r < 32; r += 8) {
        int o = o0 + r;
        float z = g_Z[((size_t)b * QKV + o) * NPIX + n0 + tx] * g_bnA[o] + g_bnB[o];
        tile[r][tx] = z > 0.f ? z : 0.f;
    }
    __syncthreads();
    bool isq = (o0 < CK);
    __half* base = isq ? g_qt2 : g_kt2;
    int oc = o0 & (CK - 1);
    __half* op = base + ((size_t)b * NPIX + n0) * KP_QK + oc;
    #pragma unroll
    for (int r = ty; r < 32; r += 8)
        op[(size_t)r * KP_QK + tx] = __float2half(tile[tx][r]);
}

// ---------------- v -> plain fp16 [b][c][m] -----------------------------------
__global__ void __launch_bounds__(256) convert_v()
{
    size_t idx = (size_t)blockIdx.x * 256 + threadIdx.x;
    int m = (int)(idx & (NPIX - 1));
    int c = (int)((idx >> 12) & (CV - 1));
    int b = (int)(idx >> 20);
    float v = g_Z[((size_t)b * QKV + 2 * CK + c) * NPIX + m];
    g_v2[idx] = __float2half(v);
}

// ---------------- launch ------------------------------------------------------
extern "C" void kernel_launch(void* const* d_in, const int* in_sizes, int n_in,
                              void* d_out, int out_size)
{
    const float* x     = (const float*)d_in[0];
    const float* wq    = (const float*)d_in[1];
    const float* bq    = (const float*)d_in[2];
    const float* gq    = (const float*)d_in[3];
    const float* betaq = (const float*)d_in[4];
    const float* wk    = (const float*)d_in[5];
    const float* bk    = (const float*)d_in[6];
    const float* gk    = (const float*)d_in[7];
    const float* betak = (const float*)d_in[8];
    const float* wv    = (const float*)d_in[9];
    const float* bv    = (const float*)d_in[10];
    const float* wW    = (const float*)d_in[11];
    const float* bW    = (const float*)d_in[12];
    float* out = (float*)d_out;

    cudaFuncSetAttribute(flash_attn, cudaFuncAttributeMaxDynamicSharedMemorySize, FL_SMEM);

    void *pwqkv2, *pwW2, *pbias, *pxt2, *pZ, *pqt2, *pkt2, *pv2, *pctx2;
    cudaGetSymbolAddress(&pwqkv2, g_wqkv2);
    cudaGetSymbolAddress(&pwW2, g_wW2);
    cudaGetSymbolAddress(&pbias, g_bias);
    cudaGetSymbolAddress(&pxt2, g_xt2);
    cudaGetSymbolAddress(&pZ, g_Z);
    cudaGetSymbolAddress(&pqt2, g_qt2);
    cudaGetSymbolAddress(&pkt2, g_kt2);
    cudaGetSymbolAddress(&pv2, g_v2);
    cudaGetSymbolAddress(&pctx2, g_ctx2);

    // 1. prep weights/bias; transpose x
    prep_w<<<(QKV * CIN) / 256, 256>>>(wq, bq, wk, bk, wv, bv, wW);
    transpose_x<<<dim3(NPIX / 32, CIN / 32, BATCH), 256>>>(x);

    // 2. qkv projection (M=768, N=4096, K=512)
    gemm_fp16<<<dim3(NPIX / 128, QKV / 128, BATCH), 256>>>(
        (const __half*)pwqkv2, (const __half*)pxt2, (float*)pZ,
        KP_X, KP_X / 32, NPIX,
        0, (size_t)NPIX * KP_X, (size_t)QKV * NPIX,
        (const float*)pbias, nullptr, 0, 1.0f);

    // 3. BN stats; 4. converts
    bn_stats<<<2 * CK, 256>>>(gq, betaq, gk, betak);
    convert_qk<<<dim3(NPIX / 32, (2 * CK) / 32, BATCH), 256>>>();
    convert_v<<<(BATCH * CV * NPIX) / 256, 256>>>();

    // 5-7. fused scores -> softmax -> ctx (writes ctx2 fp16 directly)
    flash_attn<<<dim3(NPIX / 128, BATCH), 256, FL_SMEM>>>(
        (const __half*)pkt2, (const __half*)pqt2, (const __half*)pv2, (__half*)pctx2);

    // 8. out conv + residual (M=512, N=4096, K=256)
    gemm_fp16<<<dim3(NPIX / 128, CIN / 128, BATCH), 256>>>(
        (const __half*)pwW2, (const __half*)pctx2, out,
        KP_CTX, KP_CTX / 32, NPIX,
        0, (size_t)NPIX * KP_CTX, (size_t)CIN * NPIX,
        bW, x, (size_t)CIN * NPIX, 1.0f);
}

// round 9
// speedup vs baseline: 7.0152x; 1.0143x over previous
#include <cuda_runtime.h>
#include <cuda_fp16.h>
#include <cstdint>
#include <math.h>

#define BATCH 4
#define CIN   512
#define CK    256
#define CV    256
#define QKV   768
#define NPIX  4096
#define EPSBN 1e-5f

#define KP_X   512
#define KP_QK  256
#define KP_CTX 256

// ---------------- scratch globals --------------------------------------------
static __device__ __half g_wqkv2[(size_t)QKV * KP_X];
static __device__ __half g_wW2[(size_t)CIN * KP_CTX];
static __device__ float g_bias[QKV];
static __device__ __half g_xt2[(size_t)BATCH * NPIX * KP_X];
static __device__ __half g_Zh[(size_t)BATCH * QKV * NPIX];      // fp16 qkv out [b][o][n]
static __device__ float g_stat[1024];                           // sums[512], sumsq[512]
static __device__ float g_bnA[2 * CK], g_bnB[2 * CK];
static __device__ __half g_qt2[(size_t)BATCH * NPIX * KP_QK];   // [b][m][k]
static __device__ __half g_kt2[(size_t)BATCH * NPIX * KP_QK];   // [b][n][k]
static __device__ __half g_ctx2[(size_t)BATCH * NPIX * KP_CTX]; // [b][n][c]

// ---------------- helpers ----------------------------------------------------
__device__ __forceinline__ uint32_t smem_u32(const void* p) {
    uint32_t a;
    asm("{ .reg .u64 t; cvta.to.shared.u64 t, %1; cvt.u32.u64 %0, t; }" : "=r"(a) : "l"(p));
    return a;
}
__device__ __forceinline__ void cp16(uint32_t dst, const void* src) {
    asm volatile("cp.async.cg.shared.global [%0], [%1], 16;" :: "r"(dst), "l"(src));
}
__device__ __forceinline__ void cp_commit() { asm volatile("cp.async.commit_group;" ::: "memory"); }
__device__ __forceinline__ void cp_wait1()  { asm volatile("cp.async.wait_group 1;" ::: "memory"); }

__device__ __forceinline__ uint32_t lds32(uint32_t a) {
    uint32_t v;
    asm volatile("ld.shared.b32 %0, [%1];" : "=r"(v) : "r"(a));
    return v;
}
__device__ __forceinline__ void ldsm4(uint32_t* r, uint32_t addr) {
    asm volatile("ldmatrix.sync.aligned.m8n8.x4.shared.b16 {%0,%1,%2,%3}, [%4];"
        : "=r"(r[0]), "=r"(r[1]), "=r"(r[2]), "=r"(r[3]) : "r"(addr));
}
__device__ __forceinline__ void mma16816(float* d, const uint32_t* a, uint32_t b0, uint32_t b1) {
    asm volatile(
        "mma.sync.aligned.m16n8k16.row.col.f32.f16.f16.f32 "
        "{%0,%1,%2,%3}, {%4,%5,%6,%7}, {%8,%9}, {%0,%1,%2,%3};"
        : "+f"(d[0]), "+f"(d[1]), "+f"(d[2]), "+f"(d[3])
        : "r"(a[0]), "r"(a[1]), "r"(a[2]), "r"(a[3]), "r"(b0), "r"(b1));
}
__device__ __forceinline__ uint32_t packh2(float lo, float hi) {
    __half2 h = __floats2half2_rn(lo, hi);
    return *(uint32_t*)&h;
}

// ---------------- generic fp16 NT GEMM on HMMA --------------------------------
// Writes fp32 C (with optional bias/resid) OR fp16 Ch; optional per-row BN stats
// (sum/sumsq of output rows < 512 accumulated into stats[0..511]/stats[512..1023]).
#define ROWB 80
#define OPB  10240
#define STG  20480

__global__ void __launch_bounds__(256, 2)
gemm_fp16(const __half* __restrict__ A, const __half* __restrict__ B,
          float* __restrict__ C, __half* __restrict__ Ch,
          int K, int nit, int ldc,
          size_t sA, size_t sB, size_t sC,
          const float* __restrict__ bias, const float* __restrict__ resid, size_t sR,
          float alpha, float* __restrict__ stats)
{
    __shared__ __align__(16) char smem[2 * STG];
    uint32_t sb = smem_u32(smem);
    int tid = threadIdx.x, wid = tid >> 5, lane = tid & 31;
    int bz = blockIdx.z;
    int i0 = blockIdx.y * 128;
    int j0 = blockIdx.x * 128;

    const char* ap = (const char*)(A + sA * bz);
    const char* bp = (const char*)(B + sB * bz);

    const char* asrc[2]; uint32_t adst[2];
    const char* bsrc[2]; uint32_t bdst[2];
    #pragma unroll
    for (int jj = 0; jj < 2; jj++) {
        int idx = tid + 256 * jj, row = idx >> 2, seg = idx & 3;
        asrc[jj] = ap + ((size_t)(i0 + row) * K) * 2 + seg * 16;
        adst[jj] = sb + row * ROWB + seg * 16;
        bsrc[jj] = bp + ((size_t)(j0 + row) * K) * 2 + seg * 16;
        bdst[jj] = sb + OPB + row * ROWB + seg * 16;
    }

    int g = lane >> 2, tg = lane & 3;
    int mw = wid >> 1, nw = wid & 1;
    uint32_t aB = sb + (mw * 32 + g) * ROWB + tg * 4;
    uint32_t bB = sb + OPB + (nw * 64 + g) * ROWB + tg * 4;

    float acc[2][8][4];
    #pragma unroll
    for (int t = 0; t < 2; t++)
        #pragma unroll
        for (int j = 0; j < 8; j++)
            #pragma unroll
            for (int c = 0; c < 4; c++) acc[t][j][c] = 0.f;

    #pragma unroll
    for (int jj = 0; jj < 2; jj++) { cp16(adst[jj], asrc[jj]); cp16(bdst[jj], bsrc[jj]); }
    cp_commit();

    for (int it = 0; it < nit; it++) {
        if (it + 1 < nit) {
            size_t ko = (size_t)(it + 1) * 64;
            uint32_t so = ((it + 1) & 1) * STG;
            #pragma unroll
            for (int jj = 0; jj < 2; jj++) {
                cp16(adst[jj] + so, asrc[jj] + ko);
                cp16(bdst[jj] + so, bsrc[jj] + ko);
            }
        }
        cp_commit();
        cp_wait1();
        __syncthreads();

        uint32_t so = (it & 1) * STG;
        #pragma unroll
        for (int k16 = 0; k16 < 2; k16++) {
            uint32_t kb = k16 * 32;
            uint32_t a[2][4];
            #pragma unroll
            for (int t = 0; t < 2; t++) {
                uint32_t base = aB + so + t * (16 * ROWB) + kb;
                a[t][0] = lds32(base);
                a[t][1] = lds32(base + 8 * ROWB);
                a[t][2] = lds32(base + 16);
                a[t][3] = lds32(base + 8 * ROWB + 16);
            }
            #pragma unroll
            for (int j = 0; j < 8; j++) {
                uint32_t base = bB + so + j * (8 * ROWB) + kb;
                uint32_t b0 = lds32(base);
                uint32_t b1 = lds32(base + 16);
                mma16816(acc[0][j], a[0], b0, b1);
                mma16816(acc[1][j], a[1], b0, b1);
            }
        }
        __syncthreads();
    }

    float* cb = C ? C + sC * bz : nullptr;
    __half* hb = Ch ? Ch + sC * bz : nullptr;
    const float* rb = resid ? resid + sR * bz : nullptr;
    #pragma unroll
    for (int t = 0; t < 2; t++) {
        int r0 = i0 + mw * 32 + t * 16 + g;
        int r1 = r0 + 8;
        float bi0 = bias ? bias[r0] : 0.f;
        float bi1 = bias ? bias[r1] : 0.f;
        float s0 = 0.f, q0 = 0.f, s1 = 0.f, q1 = 0.f;
        #pragma unroll
        for (int j = 0; j < 8; j++) {
            int c = j0 + nw * 64 + j * 8 + tg * 2;
            float v0 = acc[t][j][0] * alpha + bi0;
            float v1 = acc[t][j][1] * alpha + bi0;
            float v2 = acc[t][j][2] * alpha + bi1;
            float v3 = acc[t][j][3] * alpha + bi1;
            if (rb) {
                float2 x0 = *(const float2*)(rb + (size_t)r0 * ldc + c);
                float2 x1 = *(const float2*)(rb + (size_t)r1 * ldc + c);
                v0 += x0.x; v1 += x0.y; v2 += x1.x; v3 += x1.y;
            }
            s0 += v0 + v1; q0 += v0 * v0 + v1 * v1;
            s1 += v2 + v3; q1 += v2 * v2 + v3 * v3;
            if (hb) {
                *(__half2*)(hb + (size_t)r0 * ldc + c) = __floats2half2_rn(v0, v1);
                *(__half2*)(hb + (size_t)r1 * ldc + c) = __floats2half2_rn(v2, v3);
            } else {
                *(float2*)(cb + (size_t)r0 * ldc + c) = make_float2(v0, v1);
                *(float2*)(cb + (size_t)r1 * ldc + c) = make_float2(v2, v3);
            }
        }
        if (stats) {
            s0 += __shfl_xor_sync(0xffffffffu, s0, 1); s0 += __shfl_xor_sync(0xffffffffu, s0, 2);
            q0 += __shfl_xor_sync(0xffffffffu, q0, 1); q0 += __shfl_xor_sync(0xffffffffu, q0, 2);
            s1 += __shfl_xor_sync(0xffffffffu, s1, 1); s1 += __shfl_xor_sync(0xffffffffu, s1, 2);
            q1 += __shfl_xor_sync(0xffffffffu, q1, 1); q1 += __shfl_xor_sync(0xffffffffu, q1, 2);
            if (tg == 0 && r0 < 512) { atomicAdd(&stats[r0], s0); atomicAdd(&stats[512 + r0], q0); }
            if (tg == 0 && r1 < 512) { atomicAdd(&stats[r1], s1); atomicAdd(&stats[512 + r1], q1); }
        }
    }
}

// ---------------- flash attention (ldmatrix fragment loads) -------------------
#define KROW 528
#define VROW 144
#define SM_Q 67584
#define QSTG 33792
#define SM_V (67584 + 2*33792)
#define VSTG 36864
#define FL_SMEM (135168 + 2*36864)

__global__ void __launch_bounds__(256, 1)
flash_attn(const __half* __restrict__ Kt, const __half* __restrict__ Qt,
           const __half* __restrict__ Zh, __half* __restrict__ ctx2)
{
    extern __shared__ __align__(16) char smem[];
    uint32_t sb = smem_u32(smem);
    int tid = threadIdx.x, wid = tid >> 5, lane = tid & 31;
    int g = lane >> 2, tg = lane & 3;
    int b = blockIdx.y;
    int n0 = blockIdx.x * 128;

    const char* kp = (const char*)(Kt + ((size_t)b * NPIX + n0) * CK);
    const char* qp = (const char*)(Qt + (size_t)b * NPIX * CK);
    const char* vp = (const char*)(Zh + ((size_t)b * QKV + 2 * CK) * NPIX);

    #pragma unroll
    for (int j = 0; j < 16; j++) {
        int idx = tid + 256 * j, row = idx >> 5, seg = idx & 31;
        cp16(sb + row * KROW + seg * 16, kp + (size_t)row * 512 + seg * 16);
    }
    #pragma unroll
    for (int j = 0; j < 8; j++) {
        int idx = tid + 256 * j;
        int qrow = idx >> 5, qseg = idx & 31;
        cp16(sb + SM_Q + qrow * KROW + qseg * 16, qp + (size_t)qrow * 512 + qseg * 16);
        int vrow = idx >> 3, vseg = idx & 7;
        cp16(sb + SM_V + vrow * VROW + vseg * 16, vp + ((size_t)vrow * NPIX) * 2 + vseg * 16);
    }
    cp_commit();

    float o[32][4];
    #pragma unroll
    for (int j = 0; j < 32; j++)
        #pragma unroll
        for (int c = 0; c < 4; c++) o[j][c] = 0.f;
    float m0 = -1e30f, m8 = -1e30f, l0 = 0.f, l8 = 0.f;

    // ldmatrix per-lane row bases
    uint32_t arow = sb + (wid * 16 + (lane & 15)) * KROW + (lane >> 4) * 16;
    uint32_t qoff = ((lane >> 4) * 8 + (lane & 7)) * KROW + ((lane >> 3) & 1) * 16;
    uint32_t voff = ((lane >> 4) * 8 + (lane & 7)) * VROW + ((lane >> 3) & 1) * 16;

    for (int it = 0; it < NPIX / 64; it++) {
        if (it + 1 < NPIX / 64) {
            int st = (it + 1) & 1;
            size_t mo = (size_t)(it + 1) * 64;
            #pragma unroll
            for (int j = 0; j < 8; j++) {
                int idx = tid + 256 * j;
                int qrow = idx >> 5, qseg = idx & 31;
                cp16(sb + SM_Q + st * QSTG + qrow * KROW + qseg * 16,
                     qp + ((size_t)(mo + qrow)) * 512 + qseg * 16);
                int vrow = idx >> 3, vseg = idx & 7;
                cp16(sb + SM_V + st * VSTG + vrow * VROW + vseg * 16,
                     vp + ((size_t)vrow * NPIX + mo) * 2 + vseg * 16);
            }
        }
        cp_commit();
        cp_wait1();
        __syncthreads();

        int st = it & 1;
        uint32_t qb = sb + SM_Q + st * QSTG + qoff;
        uint32_t vb = sb + SM_V + st * VSTG + voff;

        // ---- gemm1: S[16n x 64m], K'=256, via ldmatrix ----
        float s[8][4];
        #pragma unroll
        for (int j = 0; j < 8; j++)
            #pragma unroll
            for (int c = 0; c < 4; c++) s[j][c] = 0.f;
        #pragma unroll
        for (int k16 = 0; k16 < 16; k16++) {
            uint32_t a[4];
            ldsm4(a, arow + k16 * 32);
            #pragma unroll
            for (int j2 = 0; j2 < 4; j2++) {
                uint32_t bq[4];
                ldsm4(bq, qb + j2 * (16 * KROW) + k16 * 32);
                mma16816(s[2 * j2],     a, bq[0], bq[1]);
                mma16816(s[2 * j2 + 1], a, bq[2], bq[3]);
            }
        }
        #pragma unroll
        for (int j = 0; j < 8; j++)
            #pragma unroll
            for (int c = 0; c < 4; c++) s[j][c] *= 0.0625f;

        // ---- online softmax ----
        float mx0 = -1e30f, mx8 = -1e30f;
        #pragma unroll
        for (int j = 0; j < 8; j++) {
            mx0 = fmaxf(mx0, fmaxf(s[j][0], s[j][1]));
            mx8 = fmaxf(mx8, fmaxf(s[j][2], s[j][3]));
        }
        mx0 = fmaxf(mx0, __shfl_xor_sync(0xffffffffu, mx0, 1));
        mx0 = fmaxf(mx0, __shfl_xor_sync(0xffffffffu, mx0, 2));
        mx8 = fmaxf(mx8, __shfl_xor_sync(0xffffffffu, mx8, 1));
        mx8 = fmaxf(mx8, __shfl_xor_sync(0xffffffffu, mx8, 2));
        float nm0 = fmaxf(m0, mx0), nm8 = fmaxf(m8, mx8);
        float sc0 = __expf(m0 - nm0), sc8 = __expf(m8 - nm8);
        m0 = nm0; m8 = nm8;

        float sum0 = 0.f, sum8 = 0.f;
        uint32_t pa[8][2];
        #pragma unroll
        for (int j = 0; j < 8; j++) {
            float p0 = __expf(s[j][0] - m0);
            float p1 = __expf(s[j][1] - m0);
            float p2 = __expf(s[j][2] - m8);
            float p3 = __expf(s[j][3] - m8);
            sum0 += p0 + p1; sum8 += p2 + p3;
            pa[j][0] = packh2(p0, p1);
            pa[j][1] = packh2(p2, p3);
        }
        sum0 += __shfl_xor_sync(0xffffffffu, sum0, 1);
        sum0 += __shfl_xor_sync(0xffffffffu, sum0, 2);
        sum8 += __shfl_xor_sync(0xffffffffu, sum8, 1);
        sum8 += __shfl_xor_sync(0xffffffffu, sum8, 2);
        l0 = l0 * sc0 + sum0;
        l8 = l8 * sc8 + sum8;

        if (sc0 != 1.f || sc8 != 1.f) {
            #pragma unroll
            for (int j = 0; j < 32; j++) {
                o[j][0] *= sc0; o[j][1] *= sc0;
                o[j][2] *= sc8; o[j][3] *= sc8;
            }
        }

        // ---- gemm2: O[16n x 256c] += P . V^T, via ldmatrix ----
        #pragma unroll
        for (int t = 0; t < 4; t++) {
            uint32_t a2[4] = { pa[2 * t][0], pa[2 * t][1], pa[2 * t + 1][0], pa[2 * t + 1][1] };
            #pragma unroll
            for (int j4 = 0; j4 < 16; j4++) {
                uint32_t bv[4];
                ldsm4(bv, vb + j4 * (16 * VROW) + t * 32);
                mma16816(o[2 * j4],     a2, bv[0], bv[1]);
                mma16816(o[2 * j4 + 1], a2, bv[2], bv[3]);
            }
        }
        __syncthreads();
    }

    float i0 = 1.f / l0, i8 = 1.f / l8;
    int nrow = n0 + wid * 16 + g;
    __half2* out0 = (__half2*)(ctx2 + ((size_t)b * NPIX + nrow) * CV);
    __half2* out8 = (__half2*)(ctx2 + ((size_t)b * NPIX + nrow + 8) * CV);
    #pragma unroll
    for (int j2 = 0; j2 < 32; j2++) {
        int cp_ = 4 * j2 + tg;
        out0[cp_] = __floats2half2_rn(o[j2][0] * i0, o[j2][1] * i0);
        out8[cp_] = __floats2half2_rn(o[j2][2] * i8, o[j2][3] * i8);
    }
}

// ---------------- prep / converts ---------------------------------------------
__global__ void __launch_bounds__(256) zero_stats()
{
    g_stat[blockIdx.x * 256 + threadIdx.x] = 0.f;
}

__global__ void __launch_bounds__(256) prep_w(
    const float* __restrict__ wq, const float* __restrict__ bq,
    const float* __restrict__ wk, const float* __restrict__ bk,
    const float* __restrict__ wv, const float* __restrict__ bv,
    const float* __restrict__ wW)
{
    int idx = blockIdx.x * 256 + threadIdx.x;
    {
        int o = idx / CIN, c = idx % CIN;
        float v = (o < CK) ? wq[o * CIN + c] : (o < 2 * CK) ? wk[(o - CK) * CIN + c]
                                                            : wv[(o - 2 * CK) * CIN + c];
        g_wqkv2[(size_t)o * KP_X + c] = __float2half(v);
    }
    if (idx < CIN * CV) {
        int co = idx / CV, cv = idx % CV;
        g_wW2[(size_t)co * KP_CTX + cv] = __float2half(wW[co * CV + cv]);
    }
    if (idx < QKV)
        g_bias[idx] = (idx < CK) ? bq[idx] : (idx < 2 * CK) ? bk[idx - CK] : bv[idx - 2 * CK];
}

__global__ void __launch_bounds__(256) transpose_x(const float* __restrict__ x)
{
    __shared__ float tile[32][33];
    int b = blockIdx.z, c0 = blockIdx.y * 32, n0 = blockIdx.x * 32;
    int tx = threadIdx.x & 31, ty = threadIdx.x >> 5;
    const float* xp = x + ((size_t)b * CIN + c0) * NPIX + n0;
    #pragma unroll
    for (int r = ty; r < 32; r += 8) tile[r][tx] = xp[(size_t)r * NPIX + tx];
    __syncthreads();
    __half* op = g_xt2 + ((size_t)b * NPIX + n0) * KP_X + c0;
    #pragma unroll
    for (int r = ty; r < 32; r += 8)
        op[(size_t)r * KP_X + tx] = __float2half(tile[tx][r]);
}

__global__ void __launch_bounds__(256) bn_finalize(
    const float* __restrict__ gq, const float* __restrict__ betaq,
    const float* __restrict__ gk, const float* __restrict__ betak)
{
    int o = blockIdx.x * 256 + threadIdx.x;   // < 512
    float cnt = (float)(BATCH * NPIX);
    float mean = g_stat[o] / cnt;
    float var = g_stat[512 + o] / cnt - mean * mean;
    float inv = rsqrtf(var + EPSBN);
    float gamma = (o < CK) ? gq[o] : gk[o - CK];
    float beta  = (o < CK) ? betaq[o] : betak[o - CK];
    g_bnA[o] = gamma * inv;
    g_bnB[o] = beta - mean * gamma * inv;
}

__global__ void __launch_bounds__(256) convert_qk()
{
    __shared__ float tile[32][33];
    int b = blockIdx.z, o0 = blockIdx.y * 32, n0 = blockIdx.x * 32;
    int tx = threadIdx.x & 31, ty = threadIdx.x >> 5;
    #pragma unroll
    for (int r = ty; r < 32; r += 8) {
        int o = o0 + r;
        float z = __half2float(g_Zh[((size_t)b * QKV + o) * NPIX + n0 + tx]) * g_bnA[o] + g_bnB[o];
        tile[r][tx] = z > 0.f ? z : 0.f;
    }
    __syncthreads();
    bool isq = (o0 < CK);
    __half* base = isq ? g_qt2 : g_kt2;
    int oc = o0 & (CK - 1);
    __half* op = base + ((size_t)b * NPIX + n0) * KP_QK + oc;
    #pragma unroll
    for (int r = ty; r < 32; r += 8)
        op[(size_t)r * KP_QK + tx] = __float2half(tile[tx][r]);
}

// ---------------- launch ------------------------------------------------------
extern "C" void kernel_launch(void* const* d_in, const int* in_sizes, int n_in,
                              void* d_out, int out_size)
{
    const float* x     = (const float*)d_in[0];
    const float* wq    = (const float*)d_in[1];
    const float* bq    = (const float*)d_in[2];
    const float* gq    = (const float*)d_in[3];
    const float* betaq = (const float*)d_in[4];
    const float* wk    = (const float*)d_in[5];
    const float* bk    = (const float*)d_in[6];
    const float* gk    = (const float*)d_in[7];
    const float* betak = (const float*)d_in[8];
    const float* wv    = (const float*)d_in[9];
    const float* bv    = (const float*)d_in[10];
    const float* wW    = (const float*)d_in[11];
    const float* bW    = (const float*)d_in[12];
    float* out = (float*)d_out;

    cudaFuncSetAttribute(flash_attn, cudaFuncAttributeMaxDynamicSharedMemorySize, FL_SMEM);

    void *pwqkv2, *pwW2, *pbias, *pxt2, *pZh, *pqt2, *pkt2, *pctx2, *pstat;
    cudaGetSymbolAddress(&pwqkv2, g_wqkv2);
    cudaGetSymbolAddress(&pwW2, g_wW2);
    cudaGetSymbolAddress(&pbias, g_bias);
    cudaGetSymbolAddress(&pxt2, g_xt2);
    cudaGetSymbolAddress(&pZh, g_Zh);
    cudaGetSymbolAddress(&pqt2, g_qt2);
    cudaGetSymbolAddress(&pkt2, g_kt2);
    cudaGetSymbolAddress(&pctx2, g_ctx2);
    cudaGetSymbolAddress(&pstat, g_stat);

    // 1. prep weights/bias; transpose x; zero stats
    prep_w<<<(QKV * CIN) / 256, 256>>>(wq, bq, wk, bk, wv, bv, wW);
    transpose_x<<<dim3(NPIX / 32, CIN / 32, BATCH), 256>>>(x);
    zero_stats<<<4, 256>>>();

    // 2. qkv projection -> fp16 Zh + fused BN partial stats
    gemm_fp16<<<dim3(NPIX / 128, QKV / 128, BATCH), 256>>>(
        (const __half*)pwqkv2, (const __half*)pxt2, nullptr, (__half*)pZh,
        KP_X, KP_X / 32, NPIX,
        0, (size_t)NPIX * KP_X, (size_t)QKV * NPIX,
        (const float*)pbias, nullptr, 0, 1.0f, (float*)pstat);

    // 3. finalize BN; BN+ReLU+transpose q/k
    bn_finalize<<<2, 256>>>(gq, betaq, gk, betak);
    convert_qk<<<dim3(NPIX / 32, (2 * CK) / 32, BATCH), 256>>>();

    // 4-6. fused scores -> softmax -> ctx (V read directly from Zh)
    flash_attn<<<dim3(NPIX / 128, BATCH), 256, FL_SMEM>>>(
        (const __half*)pkt2, (const __half*)pqt2, (const __half*)pZh, (__half*)pctx2);

    // 7. out conv + residual
    gemm_fp16<<<dim3(NPIX / 128, CIN / 128, BATCH), 256>>>(
        (const __half*)pwW2, (const __half*)pctx2, out, nullptr,
        KP_CTX, KP_CTX / 32, NPIX,
        0, (size_t)NPIX * KP_CTX, (size_t)CIN * NPIX,
        bW, x, (size_t)CIN * NPIX, 1.0f, nullptr);
}

// round 10
// speedup vs baseline: 7.3563x; 1.0486x over previous
#include <cuda_runtime.h>
#include <cuda_fp16.h>
#include <cstdint>
#include <math.h>

#define BATCH 4
#define CIN   512
#define CK    256
#define CV    256
#define QKV   768
#define NPIX  4096
#define EPSBN 1e-5f

#define KP_X   512
#define KP_QK  256
#define KP_CTX 256

// ---------------- scratch globals --------------------------------------------
static __device__ __half g_wqkv2[(size_t)QKV * KP_X];
static __device__ __half g_wW2[(size_t)CIN * KP_CTX];
static __device__ float g_bias[QKV];
static __device__ __half g_xt2[(size_t)BATCH * NPIX * KP_X];
static __device__ __half g_Zh[(size_t)BATCH * QKV * NPIX];      // fp16 qkv out [b][o][n]
static __device__ float g_stat[1024];
static __device__ float g_bnA[2 * CK], g_bnB[2 * CK];
static __device__ __half g_qt2[(size_t)BATCH * NPIX * KP_QK];
static __device__ __half g_kt2[(size_t)BATCH * NPIX * KP_QK];
static __device__ __half g_ctx2[(size_t)BATCH * NPIX * KP_CTX];

// ---------------- helpers ----------------------------------------------------
__device__ __forceinline__ uint32_t smem_u32(const void* p) {
    uint32_t a;
    asm("{ .reg .u64 t; cvta.to.shared.u64 t, %1; cvt.u32.u64 %0, t; }" : "=r"(a) : "l"(p));
    return a;
}
__device__ __forceinline__ void cp16(uint32_t dst, const void* src) {
    asm volatile("cp.async.cg.shared.global [%0], [%1], 16;" :: "r"(dst), "l"(src));
}
__device__ __forceinline__ void cp_commit() { asm volatile("cp.async.commit_group;" ::: "memory"); }
__device__ __forceinline__ void cp_wait1()  { asm volatile("cp.async.wait_group 1;" ::: "memory"); }

__device__ __forceinline__ void ldsm4(uint32_t* r, uint32_t addr) {
    asm volatile("ldmatrix.sync.aligned.m8n8.x4.shared.b16 {%0,%1,%2,%3}, [%4];"
        : "=r"(r[0]), "=r"(r[1]), "=r"(r[2]), "=r"(r[3]) : "r"(addr));
}
__device__ __forceinline__ void mma16816(float* d, const uint32_t* a, uint32_t b0, uint32_t b1) {
    asm volatile(
        "mma.sync.aligned.m16n8k16.row.col.f32.f16.f16.f32 "
        "{%0,%1,%2,%3}, {%4,%5,%6,%7}, {%8,%9}, {%0,%1,%2,%3};"
        : "+f"(d[0]), "+f"(d[1]), "+f"(d[2]), "+f"(d[3])
        : "r"(a[0]), "r"(a[1]), "r"(a[2]), "r"(a[3]), "r"(b0), "r"(b1));
}
__device__ __forceinline__ uint32_t packh2(float lo, float hi) {
    __half2 h = __floats2half2_rn(lo, hi);
    return *(uint32_t*)&h;
}
__device__ __forceinline__ uint32_t ex2h2(uint32_t t) {
    uint32_t p;
    asm("ex2.approx.f16x2 %0, %1;" : "=r"(p) : "r"(t));
    return p;
}

// ---------------- generic fp16 NT GEMM on HMMA (ldmatrix) ---------------------
#define ROWB 80
#define OPB  10240
#define STG  20480

__global__ void __launch_bounds__(256, 2)
gemm_fp16(const __half* __restrict__ A, const __half* __restrict__ B,
          float* __restrict__ C, __half* __restrict__ Ch,
          int K, int nit, int ldc,
          size_t sA, size_t sB, size_t sC,
          const float* __restrict__ bias, const float* __restrict__ resid, size_t sR,
          float alpha, float* __restrict__ stats)
{
    __shared__ __align__(16) char smem[2 * STG];
    uint32_t sb = smem_u32(smem);
    int tid = threadIdx.x, wid = tid >> 5, lane = tid & 31;
    int bz = blockIdx.z;
    int i0 = blockIdx.y * 128;
    int j0 = blockIdx.x * 128;

    const char* ap = (const char*)(A + sA * bz);
    const char* bp = (const char*)(B + sB * bz);

    const char* asrc[2]; uint32_t adst[2];
    const char* bsrc[2]; uint32_t bdst[2];
    #pragma unroll
    for (int jj = 0; jj < 2; jj++) {
        int idx = tid + 256 * jj, row = idx >> 2, seg = idx & 3;
        asrc[jj] = ap + ((size_t)(i0 + row) * K) * 2 + seg * 16;
        adst[jj] = sb + row * ROWB + seg * 16;
        bsrc[jj] = bp + ((size_t)(j0 + row) * K) * 2 + seg * 16;
        bdst[jj] = sb + OPB + row * ROWB + seg * 16;
    }

    int g = lane >> 2, tg = lane & 3;
    int mw = wid >> 1, nw = wid & 1;
    // ldmatrix bases (validated mapping from flash kernel)
    uint32_t arow = sb + (mw * 32 + (lane & 15)) * ROWB + (lane >> 4) * 16;
    uint32_t brow = sb + OPB + (nw * 64 + (lane >> 4) * 8 + (lane & 7)) * ROWB
                  + ((lane >> 3) & 1) * 16;

    float acc[2][8][4];
    #pragma unroll
    for (int t = 0; t < 2; t++)
        #pragma unroll
        for (int j = 0; j < 8; j++)
            #pragma unroll
            for (int c = 0; c < 4; c++) acc[t][j][c] = 0.f;

    #pragma unroll
    for (int jj = 0; jj < 2; jj++) { cp16(adst[jj], asrc[jj]); cp16(bdst[jj], bsrc[jj]); }
    cp_commit();

    for (int it = 0; it < nit; it++) {
        if (it + 1 < nit) {
            size_t ko = (size_t)(it + 1) * 64;
            uint32_t so = ((it + 1) & 1) * STG;
            #pragma unroll
            for (int jj = 0; jj < 2; jj++) {
                cp16(adst[jj] + so, asrc[jj] + ko);
                cp16(bdst[jj] + so, bsrc[jj] + ko);
            }
        }
        cp_commit();
        cp_wait1();
        __syncthreads();

        uint32_t so = (it & 1) * STG;
        #pragma unroll
        for (int k16 = 0; k16 < 2; k16++) {
            uint32_t kb = k16 * 32;
            uint32_t a0[4], a1[4];
            ldsm4(a0, arow + so + kb);
            ldsm4(a1, arow + 16 * ROWB + so + kb);
            #pragma unroll
            for (int j2 = 0; j2 < 4; j2++) {
                uint32_t bq[4];
                ldsm4(bq, brow + so + j2 * (16 * ROWB) + kb);
                mma16816(acc[0][2 * j2],     a0, bq[0], bq[1]);
                mma16816(acc[0][2 * j2 + 1], a0, bq[2], bq[3]);
                mma16816(acc[1][2 * j2],     a1, bq[0], bq[1]);
                mma16816(acc[1][2 * j2 + 1], a1, bq[2], bq[3]);
            }
        }
        __syncthreads();
    }

    float* cb = C ? C + sC * bz : nullptr;
    __half* hb = Ch ? Ch + sC * bz : nullptr;
    const float* rb = resid ? resid + sR * bz : nullptr;
    #pragma unroll
    for (int t = 0; t < 2; t++) {
        int r0 = i0 + mw * 32 + t * 16 + g;
        int r1 = r0 + 8;
        float bi0 = bias ? bias[r0] : 0.f;
        float bi1 = bias ? bias[r1] : 0.f;
        float s0 = 0.f, q0 = 0.f, s1 = 0.f, q1 = 0.f;
        #pragma unroll
        for (int j = 0; j < 8; j++) {
            int c = j0 + nw * 64 + j * 8 + tg * 2;
            float v0 = acc[t][j][0] * alpha + bi0;
            float v1 = acc[t][j][1] * alpha + bi0;
            float v2 = acc[t][j][2] * alpha + bi1;
            float v3 = acc[t][j][3] * alpha + bi1;
            if (rb) {
                float2 x0 = *(const float2*)(rb + (size_t)r0 * ldc + c);
                float2 x1 = *(const float2*)(rb + (size_t)r1 * ldc + c);
                v0 += x0.x; v1 += x0.y; v2 += x1.x; v3 += x1.y;
            }
            s0 += v0 + v1; q0 += v0 * v0 + v1 * v1;
            s1 += v2 + v3; q1 += v2 * v2 + v3 * v3;
            if (hb) {
                *(__half2*)(hb + (size_t)r0 * ldc + c) = __floats2half2_rn(v0, v1);
                *(__half2*)(hb + (size_t)r1 * ldc + c) = __floats2half2_rn(v2, v3);
            } else {
                *(float2*)(cb + (size_t)r0 * ldc + c) = make_float2(v0, v1);
                *(float2*)(cb + (size_t)r1 * ldc + c) = make_float2(v2, v3);
            }
        }
        if (stats) {
            s0 += __shfl_xor_sync(0xffffffffu, s0, 1); s0 += __shfl_xor_sync(0xffffffffu, s0, 2);
            q0 += __shfl_xor_sync(0xffffffffu, q0, 1); q0 += __shfl_xor_sync(0xffffffffu, q0, 2);
            s1 += __shfl_xor_sync(0xffffffffu, s1, 1); s1 += __shfl_xor_sync(0xffffffffu, s1, 2);
            q1 += __shfl_xor_sync(0xffffffffu, q1, 1); q1 += __shfl_xor_sync(0xffffffffu, q1, 2);
            if (tg == 0 && r0 < 512) { atomicAdd(&stats[r0], s0); atomicAdd(&stats[512 + r0], q0); }
            if (tg == 0 && r1 < 512) { atomicAdd(&stats[r1], s1); atomicAdd(&stats[512 + r1], q1); }
        }
    }
}

// ---------------- flash attention ---------------------------------------------
#define KROW 528
#define VROW 144
#define SM_Q 67584
#define QSTG 33792
#define SM_V (67584 + 2*33792)
#define VSTG 36864
#define FL_SMEM (135168 + 2*36864)
#define LOG2E 1.44269504f

__global__ void __launch_bounds__(256, 1)
flash_attn(const __half* __restrict__ Kt, const __half* __restrict__ Qt,
           const __half* __restrict__ Zh, __half* __restrict__ ctx2)
{
    extern __shared__ __align__(16) char smem[];
    uint32_t sb = smem_u32(smem);
    int tid = threadIdx.x, wid = tid >> 5, lane = tid & 31;
    int g = lane >> 2, tg = lane & 3;
    int b = blockIdx.y;
    int n0 = blockIdx.x * 128;

    const char* kp = (const char*)(Kt + ((size_t)b * NPIX + n0) * CK);
    const char* qp = (const char*)(Qt + (size_t)b * NPIX * CK);
    const char* vp = (const char*)(Zh + ((size_t)b * QKV + 2 * CK) * NPIX);

    #pragma unroll
    for (int j = 0; j < 16; j++) {
        int idx = tid + 256 * j, row = idx >> 5, seg = idx & 31;
        cp16(sb + row * KROW + seg * 16, kp + (size_t)row * 512 + seg * 16);
    }
    #pragma unroll
    for (int j = 0; j < 8; j++) {
        int idx = tid + 256 * j;
        int qrow = idx >> 5, qseg = idx & 31;
        cp16(sb + SM_Q + qrow * KROW + qseg * 16, qp + (size_t)qrow * 512 + qseg * 16);
        int vrow = idx >> 3, vseg = idx & 7;
        cp16(sb + SM_V + vrow * VROW + vseg * 16, vp + ((size_t)vrow * NPIX) * 2 + vseg * 16);
    }
    cp_commit();

    float o[32][4];
    #pragma unroll
    for (int j = 0; j < 32; j++)
        #pragma unroll
        for (int c = 0; c < 4; c++) o[j][c] = 0.f;
    float osum[4] = {0.f, 0.f, 0.f, 0.f};   // row sums of P via ones-mma
    float m0 = -1e30f, m8 = -1e30f;

    uint32_t arow = sb + (wid * 16 + (lane & 15)) * KROW + (lane >> 4) * 16;
    uint32_t qoff = ((lane >> 4) * 8 + (lane & 7)) * KROW + ((lane >> 3) & 1) * 16;
    uint32_t voff = ((lane >> 4) * 8 + (lane & 7)) * VROW + ((lane >> 3) & 1) * 16;
    const uint32_t ONESH2 = 0x3C003C00u;

    for (int it = 0; it < NPIX / 64; it++) {
        if (it + 1 < NPIX / 64) {
            int st = (it + 1) & 1;
            size_t mo = (size_t)(it + 1) * 64;
            #pragma unroll
            for (int j = 0; j < 8; j++) {
                int idx = tid + 256 * j;
                int qrow = idx >> 5, qseg = idx & 31;
                cp16(sb + SM_Q + st * QSTG + qrow * KROW + qseg * 16,
                     qp + ((size_t)(mo + qrow)) * 512 + qseg * 16);
                int vrow = idx >> 3, vseg = idx & 7;
                cp16(sb + SM_V + st * VSTG + vrow * VROW + vseg * 16,
                     vp + ((size_t)vrow * NPIX + mo) * 2 + vseg * 16);
            }
        }
        cp_commit();
        cp_wait1();
        __syncthreads();

        int st = it & 1;
        uint32_t qb = sb + SM_Q + st * QSTG + qoff;
        uint32_t vb = sb + SM_V + st * VSTG + voff;

        // ---- gemm1: S[16n x 64m], K'=256 ----
        float s[8][4];
        #pragma unroll
        for (int j = 0; j < 8; j++)
            #pragma unroll
            for (int c = 0; c < 4; c++) s[j][c] = 0.f;
        #pragma unroll
        for (int k16 = 0; k16 < 16; k16++) {
            uint32_t a[4];
            ldsm4(a, arow + k16 * 32);
            #pragma unroll
            for (int j2 = 0; j2 < 4; j2++) {
                uint32_t bq[4];
                ldsm4(bq, qb + j2 * (16 * KROW) + k16 * 32);
                mma16816(s[2 * j2],     a, bq[0], bq[1]);
                mma16816(s[2 * j2 + 1], a, bq[2], bq[3]);
            }
        }
        #pragma unroll
        for (int j = 0; j < 8; j++)
            #pragma unroll
            for (int c = 0; c < 4; c++) s[j][c] *= 0.0625f;

        // ---- online softmax (f16x2 exp; sums via ones-mma below) ----
        float mx0 = -1e30f, mx8 = -1e30f;
        #pragma unroll
        for (int j = 0; j < 8; j++) {
            mx0 = fmaxf(mx0, fmaxf(s[j][0], s[j][1]));
            mx8 = fmaxf(mx8, fmaxf(s[j][2], s[j][3]));
        }
        mx0 = fmaxf(mx0, __shfl_xor_sync(0xffffffffu, mx0, 1));
        mx0 = fmaxf(mx0, __shfl_xor_sync(0xffffffffu, mx0, 2));
        mx8 = fmaxf(mx8, __shfl_xor_sync(0xffffffffu, mx8, 1));
        mx8 = fmaxf(mx8, __shfl_xor_sync(0xffffffffu, mx8, 2));
        float nm0 = fmaxf(m0, mx0), nm8 = fmaxf(m8, mx8);
        float sc0 = __expf(m0 - nm0), sc8 = __expf(m8 - nm8);
        m0 = nm0; m8 = nm8;
        float c0 = m0 * LOG2E, c8 = m8 * LOG2E;

        uint32_t pa[8][2];
        #pragma unroll
        for (int j = 0; j < 8; j++) {
            float t0 = fmaf(s[j][0], LOG2E, -c0);
            float t1 = fmaf(s[j][1], LOG2E, -c0);
            float t2 = fmaf(s[j][2], LOG2E, -c8);
            float t3 = fmaf(s[j][3], LOG2E, -c8);
            pa[j][0] = ex2h2(packh2(t0, t1));
            pa[j][1] = ex2h2(packh2(t2, t3));
        }

        if (sc0 != 1.f || sc8 != 1.f) {
            #pragma unroll
            for (int j = 0; j < 32; j++) {
                o[j][0] *= sc0; o[j][1] *= sc0;
                o[j][2] *= sc8; o[j][3] *= sc8;
            }
            osum[0] *= sc0; osum[1] *= sc0;
            osum[2] *= sc8; osum[3] *= sc8;
        }

        // ---- gemm2: O += P.V^T ; row-sums via ones-mma ----
        #pragma unroll
        for (int t = 0; t < 4; t++) {
            uint32_t a2[4] = { pa[2 * t][0], pa[2 * t][1], pa[2 * t + 1][0], pa[2 * t + 1][1] };
            mma16816(osum, a2, ONESH2, ONESH2);
            #pragma unroll
            for (int j4 = 0; j4 < 16; j4++) {
                uint32_t bv[4];
                ldsm4(bv, vb + j4 * (16 * VROW) + t * 32);
                mma16816(o[2 * j4],     a2, bv[0], bv[1]);
                mma16816(o[2 * j4 + 1], a2, bv[2], bv[3]);
            }
        }
        __syncthreads();
    }

    float i0 = 1.f / osum[0], i8 = 1.f / osum[2];
    int nrow = n0 + wid * 16 + g;
    __half2* out0 = (__half2*)(ctx2 + ((size_t)b * NPIX + nrow) * CV);
    __half2* out8 = (__half2*)(ctx2 + ((size_t)b * NPIX + nrow + 8) * CV);
    #pragma unroll
    for (int j2 = 0; j2 < 32; j2++) {
        int cp_ = 4 * j2 + tg;
        out0[cp_] = __floats2half2_rn(o[j2][0] * i0, o[j2][1] * i0);
        out8[cp_] = __floats2half2_rn(o[j2][2] * i8, o[j2][3] * i8);
    }
}

// ---------------- prep / converts ---------------------------------------------
__global__ void __launch_bounds__(256) zero_stats()
{
    g_stat[blockIdx.x * 256 + threadIdx.x] = 0.f;
}

__global__ void __launch_bounds__(256) prep_w(
    const float* __restrict__ wq, const float* __restrict__ bq,
    const float* __restrict__ wk, const float* __restrict__ bk,
    const float* __restrict__ wv, const float* __restrict__ bv,
    const float* __restrict__ wW)
{
    int idx = blockIdx.x * 256 + threadIdx.x;
    {
        int o = idx / CIN, c = idx % CIN;
        float v = (o < CK) ? wq[o * CIN + c] : (o < 2 * CK) ? wk[(o - CK) * CIN + c]
                                                            : wv[(o - 2 * CK) * CIN + c];
        g_wqkv2[(size_t)o * KP_X + c] = __float2half(v);
    }
    if (idx < CIN * CV) {
        int co = idx / CV, cv = idx % CV;
        g_wW2[(size_t)co * KP_CTX + cv] = __float2half(wW[co * CV + cv]);
    }
    if (idx < QKV)
        g_bias[idx] = (idx < CK) ? bq[idx] : (idx < 2 * CK) ? bk[idx - CK] : bv[idx - 2 * CK];
}

__global__ void __launch_bounds__(256) transpose_x(const float* __restrict__ x)
{
    __shared__ float tile[32][33];
    int b = blockIdx.z, c0 = blockIdx.y * 32, n0 = blockIdx.x * 32;
    int tx = threadIdx.x & 31, ty = threadIdx.x >> 5;
    const float* xp = x + ((size_t)b * CIN + c0) * NPIX + n0;
    #pragma unroll
    for (int r = ty; r < 32; r += 8) tile[r][tx] = xp[(size_t)r * NPIX + tx];
    __syncthreads();
    __half* op = g_xt2 + ((size_t)b * NPIX + n0) * KP_X + c0;
    #pragma unroll
    for (int r = ty; r < 32; r += 8)
        op[(size_t)r * KP_X + tx] = __float2half(tile[tx][r]);
}

__global__ void __launch_bounds__(256) bn_finalize(
    const float* __restrict__ gq, const float* __restrict__ betaq,
    const float* __restrict__ gk, const float* __restrict__ betak)
{
    int o = blockIdx.x * 256 + threadIdx.x;   // < 512
    float cnt = (float)(BATCH * NPIX);
    float mean = g_stat[o] / cnt;
    float var = g_stat[512 + o] / cnt - mean * mean;
    float inv = rsqrtf(var + EPSBN);
    float gamma = (o < CK) ? gq[o] : gk[o - CK];
    float beta  = (o < CK) ? betaq[o] : betak[o - CK];
    g_bnA[o] = gamma * inv;
    g_bnB[o] = beta - mean * gamma * inv;
}

__global__ void __launch_bounds__(256) convert_qk()
{
    __shared__ float tile[32][33];
    int b = blockIdx.z, o0 = blockIdx.y * 32, n0 = blockIdx.x * 32;
    int tx = threadIdx.x & 31, ty = threadIdx.x >> 5;
    #pragma unroll
    for (int r = ty; r < 32; r += 8) {
        int o = o0 + r;
        float z = __half2float(g_Zh[((size_t)b * QKV + o) * NPIX + n0 + tx]) * g_bnA[o] + g_bnB[o];
        tile[r][tx] = z > 0.f ? z : 0.f;
    }
    __syncthreads();
    bool isq = (o0 < CK);
    __half* base = isq ? g_qt2 : g_kt2;
    int oc = o0 & (CK - 1);
    __half* op = base + ((size_t)b * NPIX + n0) * KP_QK + oc;
    #pragma unroll
    for (int r = ty; r < 32; r += 8)
        op[(size_t)r * KP_QK + tx] = __float2half(tile[tx][r]);
}

// ---------------- launch ------------------------------------------------------
extern "C" void kernel_launch(void* const* d_in, const int* in_sizes, int n_in,
                              void* d_out, int out_size)
{
    const float* x     = (const float*)d_in[0];
    const float* wq    = (const float*)d_in[1];
    const float* bq    = (const float*)d_in[2];
    const float* gq    = (const float*)d_in[3];
    const float* betaq = (const float*)d_in[4];
    const float* wk    = (const float*)d_in[5];
    const float* bk    = (const float*)d_in[6];
    const float* gk    = (const float*)d_in[7];
    const float* betak = (const float*)d_in[8];
    const float* wv    = (const float*)d_in[9];
    const float* bv    = (const float*)d_in[10];
    const float* wW    = (const float*)d_in[11];
    const float* bW    = (const float*)d_in[12];
    float* out = (float*)d_out;

    cudaFuncSetAttribute(flash_attn, cudaFuncAttributeMaxDynamicSharedMemorySize, FL_SMEM);

    void *pwqkv2, *pwW2, *pbias, *pxt2, *pZh, *pqt2, *pkt2, *pctx2, *pstat;
    cudaGetSymbolAddress(&pwqkv2, g_wqkv2);
    cudaGetSymbolAddress(&pwW2, g_wW2);
    cudaGetSymbolAddress(&pbias, g_bias);
    cudaGetSymbolAddress(&pxt2, g_xt2);
    cudaGetSymbolAddress(&pZh, g_Zh);
    cudaGetSymbolAddress(&pqt2, g_qt2);
    cudaGetSymbolAddress(&pkt2, g_kt2);
    cudaGetSymbolAddress(&pctx2, g_ctx2);
    cudaGetSymbolAddress(&pstat, g_stat);

    // 1. prep weights/bias; transpose x; zero stats
    prep_w<<<(QKV * CIN) / 256, 256>>>(wq, bq, wk, bk, wv, bv, wW);
    transpose_x<<<dim3(NPIX / 32, CIN / 32, BATCH), 256>>>(x);
    zero_stats<<<4, 256>>>();

    // 2. qkv projection -> fp16 Zh + fused BN stats
    gemm_fp16<<<dim3(NPIX / 128, QKV / 128, BATCH), 256>>>(
        (const __half*)pwqkv2, (const __half*)pxt2, nullptr, (__half*)pZh,
        KP_X, KP_X / 32, NPIX,
        0, (size_t)NPIX * KP_X, (size_t)QKV * NPIX,
        (const float*)pbias, nullptr, 0, 1.0f, (float*)pstat);

    // 3. finalize BN; BN+ReLU+transpose q/k
    bn_finalize<<<2, 256>>>(gq, betaq, gk, betak);
    convert_qk<<<dim3(NPIX / 32, (2 * CK) / 32, BATCH), 256>>>();

    // 4-6. fused attention
    flash_attn<<<dim3(NPIX / 128, BATCH), 256, FL_SMEM>>>(
        (const __half*)pkt2, (const __half*)pqt2, (const __half*)pZh, (__half*)pctx2);

    // 7. out conv + residual
    gemm_fp16<<<dim3(NPIX / 128, CIN / 128, BATCH), 256>>>(
        (const __half*)pwW2, (const __half*)pctx2, out, nullptr,
        KP_CTX, KP_CTX / 32, NPIX,
        0, (size_t)NPIX * KP_CTX, (size_t)CIN * NPIX,
        bW, x, (size_t)CIN * NPIX, 1.0f, nullptr);
}